// round 12
// baseline (speedup 1.0000x reference)
#include <cuda_runtime.h>
#include <cuda_bf16.h>
#include <cuda_fp16.h>
#include <cstdint>

#define NB   8
#define SEQ  2048
#define ED   1024
#define HD   64

__device__ float    g_q[NB * SEQ * HD];
__device__ uint32_t g_k16[NB * SEQ * 32];   // fp16x2-packed K
__device__ uint32_t g_v16[NB * SEQ * 32];   // fp16x2-packed V
__device__ uint32_t g_wa[192 * 256];        // W digit-A (int8 x4 packed, scale 512)
__device__ uint32_t g_wb[192 * 256];        // W digit-B (scale 131072)

// ---------------- helpers ----------------
__device__ __forceinline__ void mma_f16(float* d, const uint32_t* a, const uint32_t* b) {
    asm("mma.sync.aligned.m16n8k16.row.col.f32.f16.f16.f32 "
        "{%0,%1,%2,%3}, {%4,%5,%6,%7}, {%8,%9}, {%0,%1,%2,%3};"
        : "+f"(d[0]), "+f"(d[1]), "+f"(d[2]), "+f"(d[3])
        : "r"(a[0]), "r"(a[1]), "r"(a[2]), "r"(a[3]), "r"(b[0]), "r"(b[1]));
}
__device__ __forceinline__ void mma_s8(int* d, const uint32_t* a, const uint32_t* b) {
    asm("mma.sync.aligned.m16n8k32.row.col.s32.s8.s8.s32 "
        "{%0,%1,%2,%3}, {%4,%5,%6,%7}, {%8,%9}, {%0,%1,%2,%3};"
        : "+r"(d[0]), "+r"(d[1]), "+r"(d[2]), "+r"(d[3])
        : "r"(a[0]), "r"(a[1]), "r"(a[2]), "r"(a[3]), "r"(b[0]), "r"(b[1]));
}
__device__ __forceinline__ uint32_t packh2(float a, float b) {
    __half2 h = __floats2half2_rn(a, b);
    return *(uint32_t*)&h;
}
__device__ __forceinline__ uint32_t ex2h2(uint32_t in) {
    uint32_t r;
    asm("ex2.approx.f16x2 %0, %1;" : "=r"(r) : "r"(in));
    return r;
}
__device__ __forceinline__ void split2h(float a, float b, uint32_t& hi, uint32_t& lo) {
    __half2 h2 = __floats2half2_rn(a, b);
    float ar = a - __half2float(__low2half(h2));
    float br = b - __half2float(__high2half(h2));
    __half2 l2 = __floats2half2_rn(ar, br);
    hi = *(uint32_t*)&h2;
    lo = *(uint32_t*)&l2;
}
__device__ __forceinline__ int q1(float f, float s) {
    return __float2int_rn(fminf(fmaxf(f * s, -127.f), 127.f));
}
__device__ __forceinline__ uint32_t pack4(int i0, int i1, int i2, int i3) {
    return (uint32_t)(i0 & 255) | ((uint32_t)(i1 & 255) << 8) |
           ((uint32_t)(i2 & 255) << 16) | ((uint32_t)(i3 & 255) << 24);
}
// quantize 4 floats into two int8 digits (packed): f ~ A/sA + B/(sA*sB)
__device__ __forceinline__ void quant4(float4 f, float sA, float invA, float sB,
                                       uint32_t& qa, uint32_t& qb) {
    int a0 = q1(f.x, sA), a1 = q1(f.y, sA), a2 = q1(f.z, sA), a3 = q1(f.w, sA);
    float r0 = fmaf((float)a0, -invA, f.x);
    float r1 = fmaf((float)a1, -invA, f.y);
    float r2 = fmaf((float)a2, -invA, f.z);
    float r3 = fmaf((float)a3, -invA, f.w);
    int b0 = q1(r0, sB), b1 = q1(r1, sB), b2 = q1(r2, sB), b3 = q1(r3, sB);
    qa = pack4(a0, a1, a2, a3);
    qb = pack4(b0, b1, b2, b3);
}

#define CP_ASYNC16(dst, src) \
    asm volatile("cp.async.cg.shared.global [%0], [%1], 16;" :: "r"(dst), "l"(src) : "memory")
#define CP_COMMIT() asm volatile("cp.async.commit_group;" ::: "memory")
#define CP_WAIT1()  asm volatile("cp.async.wait_group 1;" ::: "memory")
#define CP_WAIT0()  asm volatile("cp.async.wait_group 0;" ::: "memory")
#define LDSM4T(d0, d1, d2, d3, a) \
    asm volatile("ldmatrix.sync.aligned.m8n8.x4.trans.shared.b16 {%0,%1,%2,%3}, [%4];" \
                 : "=r"(d0), "=r"(d1), "=r"(d2), "=r"(d3) : "r"(a))

// ---------------------------------------------------------------------------
// Prep: quantize W (q|k|v stacked, 192x1024) into two packed int8 digits.
// ---------------------------------------------------------------------------
__global__ void prep_w(const float* __restrict__ Wq, const float* __restrict__ Wk,
                       const float* __restrict__ Wv)
{
    int idx = blockIdx.x * 256 + threadIdx.x;    // 49152 u32 slots
    int row = idx >> 8;
    int wdd = idx & 255;
    const float* src = (row < 64)  ? Wq + (size_t)row * ED
                     : (row < 128) ? Wk + (size_t)(row - 64) * ED
                                   : Wv + (size_t)(row - 128) * ED;
    float4 f = *(const float4*)(src + wdd * 4);
    uint32_t qa, qb;
    quant4(f, 512.f, 1.f / 512.f, 131072.f, qa, qb);
    g_wa[idx] = qa;
    g_wb[idx] = qb;
}

// ---------------------------------------------------------------------------
// QKV via int8 m16n8k32 IMMA, dual-digit fixed point:
//   q = accA/8192 + accC/2097152,  accA = Xa*Wa, accC = Xa*Wb + Xb*Wa.
// BM=64; N=192 in TWO passes of 96 cols. 256 CTAs x 8 warps, 2 CTAs/SM.
// ---------------------------------------------------------------------------
__global__ __launch_bounds__(256, 2)
void qkv_kernel(const float* __restrict__ x,
                const float* __restrict__ bq, const float* __restrict__ bk,
                const float* __restrict__ bv)
{
    __shared__ uint32_t xa[64][12], xb[64][12];
    __shared__ uint32_t wa[96][12], wb[96][12];

    const int t    = threadIdx.x;
    const int lane = t & 31;
    const int wid  = t >> 5;
    const int wm   = wid & 1;       // 32-row half
    const int wn   = wid >> 1;      // 24-col slice of the 96
    const int gq   = lane >> 2;
    const int tg   = lane & 3;
    const size_t rowBase = (size_t)blockIdx.x * 64;

    const int xr  = t >> 2;         // x loader row
    const int xw2 = (t & 3) * 2;    // x loader word pair (8 floats)

    const float S1 = 1.f / 8192.f, S2 = 1.f / 2097152.f;

    for (int pass = 0; pass < 2; pass++) {
        int accA[2][3][4], accC[2][3][4];
        #pragma unroll
        for (int mi = 0; mi < 2; mi++)
            #pragma unroll
            for (int ni = 0; ni < 3; ni++)
                #pragma unroll
                for (int j = 0; j < 4; j++) { accA[mi][ni][j] = 0; accC[mi][ni][j] = 0; }

        for (int ch = 0; ch < 32; ch++) {
            __syncthreads();
            // x tile: 8 floats/thread -> 2 digit pairs
            {
                const float* xp = x + (rowBase + xr) * ED + ch * 32 + xw2 * 4;
                float4 f0 = *(const float4*)xp;
                float4 f1 = *(const float4*)(xp + 4);
                uint2 qa, qb;
                quant4(f0, 16.f, 1.f / 16.f, 4096.f, qa.x, qb.x);
                quant4(f1, 16.f, 1.f / 16.f, 4096.f, qa.y, qb.y);
                *(uint2*)&xa[xr][xw2] = qa;
                *(uint2*)&xb[xr][xw2] = qb;
            }
            // W tile: 96 rows x 8 u32 per digit = 192 uint4 loads (t < 192)
            if (t < 192) {
                int r  = t >> 1;            // 0..95
                int w4 = (t & 1) * 4;       // 0 or 4
                size_t go = (size_t)(pass * 96 + r) * 256 + ch * 8 + w4;
                *(uint4*)&wa[r][w4] = *(const uint4*)&g_wa[go];
                *(uint4*)&wb[r][w4] = *(const uint4*)&g_wb[go];
            }
            __syncthreads();

            uint32_t xaf[2][4], xbf[2][4];
            #pragma unroll
            for (int mi = 0; mi < 2; mi++) {
                int r0 = wm * 32 + mi * 16 + gq;
                xaf[mi][0] = xa[r0][tg];     xaf[mi][1] = xa[r0 + 8][tg];
                xaf[mi][2] = xa[r0][tg + 4]; xaf[mi][3] = xa[r0 + 8][tg + 4];
                xbf[mi][0] = xb[r0][tg];     xbf[mi][1] = xb[r0 + 8][tg];
                xbf[mi][2] = xb[r0][tg + 4]; xbf[mi][3] = xb[r0 + 8][tg + 4];
            }
            #pragma unroll
            for (int ni = 0; ni < 3; ni++) {
                int n0 = wn * 24 + ni * 8 + gq;
                uint32_t waf[2] = {wa[n0][tg], wa[n0][tg + 4]};
                uint32_t wbf[2] = {wb[n0][tg], wb[n0][tg + 4]};
                #pragma unroll
                for (int mi = 0; mi < 2; mi++) {
                    mma_s8(accA[mi][ni], xaf[mi], waf);
                    mma_s8(accC[mi][ni], xaf[mi], wbf);
                    mma_s8(accC[mi][ni], xbf[mi], waf);
                }
            }
        }

        // epilogue for cols [pass*96, pass*96+96)
        #pragma unroll
        for (int ni = 0; ni < 3; ni++) {
            const int gc0 = pass * 96 + wn * 24 + ni * 8;
            const int wi  = gc0 >> 6;
            const int h0  = (gc0 & 63) + tg * 2;
            const float* bp = (wi == 0) ? bq : (wi == 1) ? bk : bv;
            const float b0 = bp[h0], b1 = bp[h0 + 1];
            #pragma unroll
            for (int mi = 0; mi < 2; mi++) {
                size_t r = rowBase + wm * 32 + mi * 16 + gq;
                float v0 = (float)accA[mi][ni][0] * S1 + (float)accC[mi][ni][0] * S2 + b0;
                float v1 = (float)accA[mi][ni][1] * S1 + (float)accC[mi][ni][1] * S2 + b1;
                float v2 = (float)accA[mi][ni][2] * S1 + (float)accC[mi][ni][2] * S2 + b0;
                float v3 = (float)accA[mi][ni][3] * S1 + (float)accC[mi][ni][3] * S2 + b1;
                if (wi == 0) {
                    *(float2*)(g_q + r * HD + h0)       = make_float2(v0, v1);
                    *(float2*)(g_q + (r + 8) * HD + h0) = make_float2(v2, v3);
                } else {
                    uint32_t* outp = (wi == 1) ? g_k16 : g_v16;
                    int hp = ((gc0 & 63) >> 1) + tg;
                    outp[r * 32 + hp]       = packh2(v0, v1);
                    outp[(r + 8) * 32 + hp] = packh2(v2, v3);
                }
            }
        }
        __syncthreads();   // smem reuse safety across passes
    }
}

// ---------------------------------------------------------------------------
// Causal flash attention v6 (unchanged from round 10 — 34us, near MMA floor).
// ---------------------------------------------------------------------------
#define GROUP_BAR(gid) asm volatile("bar.sync %0, 128;" :: "r"((gid) + 1) : "memory")
#define ATTN_SMEM (147456)

extern __shared__ uint32_t sbuf[];

__global__ __launch_bounds__(512, 1)
void attn_kernel(float* __restrict__ out)
{
    const int t    = threadIdx.x;
    const int lane = t & 31;
    const int wid  = t >> 5;
    const int g    = wid >> 2;
    const int qb   = wid & 3;
    const int gq   = lane >> 2;
    const int tg   = lane & 3;
    const int tl   = t & 127;
    const int b    = blockIdx.y;
    const size_t bOff  = (size_t)b * SEQ * HD;
    const size_t bOffH = (size_t)b * SEQ * 32;

    const uint32_t gbase = g * 9216;
    const uint32_t smem0 = (uint32_t)__cvta_generic_to_shared(sbuf);
    float* obuf = (float*)sbuf;
    float* mlb  = (float*)(sbuf + 4352);

    const uint32_t vlane = (uint32_t)(((lane & 7) + ((lane >> 3) & 1) * 8) * 144
                                      + (lane >> 4) * 16);

    const float SC2 = 0.18033688f;     // log2(e) / 8

    for (int pass = 0; pass < 2; pass++) {
        __syncthreads();
        const int qt = pass ? (31 - blockIdx.x) : blockIdx.x;
        const int qbase = qt * 64;
        const int r0l = qb * 16 + gq;

        uint32_t qh2[4][4], ql2[4][4];
        {
            const float* qp = g_q + bOff + (size_t)(qbase + r0l) * HD;
            #pragma unroll
            for (int c = 0; c < 4; c++) {
                int c0 = c * 16 + tg * 2;
                float2 f00 = *(const float2*)(qp + c0);
                float2 f10 = *(const float2*)(qp + 8 * HD + c0);
                float2 f01 = *(const float2*)(qp + c0 + 8);
                float2 f11 = *(const float2*)(qp + 8 * HD + c0 + 8);
                split2h(f00.x * SC2, f00.y * SC2, qh2[c][0], ql2[c][0]);
                split2h(f10.x * SC2, f10.y * SC2, qh2[c][1], ql2[c][1]);
                split2h(f01.x * SC2, f01.y * SC2, qh2[c][2], ql2[c][2]);
                split2h(f11.x * SC2, f11.y * SC2, qh2[c][3], ql2[c][3]);
            }
        }

        float m0 = -1e30f, m1 = -1e30f;
        float lacc[4] = {0.f, 0.f, 0.f, 0.f};
        float O[8][4];
        #pragma unroll
        for (int nh = 0; nh < 8; nh++)
            #pragma unroll
            for (int j = 0; j < 4; j++) O[nh][j] = 0.f;

        const int ng = (qt >= g) ? (((qt - g) >> 2) + 1) : 0;

        #define ISSUE_CP(KB, BUFI) do {                                           \
            uint32_t dstK = smem0 + (gbase + (BUFI) * 4608) * 4;                  \
            uint32_t dstV = dstK + 9216;                                          \
            _Pragma("unroll")                                                     \
            for (int i = 0; i < 4; i++) {                                         \
                int idx = tl + 128 * i;                                           \
                int row = idx >> 3, c = idx & 7;                                  \
                uint32_t so = (uint32_t)(row * 144 + c * 16);                     \
                const uint32_t* sk = g_k16 + bOffH + (size_t)((KB) + row) * 32 + c * 4; \
                const uint32_t* sv = g_v16 + bOffH + (size_t)((KB) + row) * 32 + c * 4; \
                CP_ASYNC16(dstK + so, sk);                                        \
                CP_ASYNC16(dstV + so, sv);                                        \
            }                                                                     \
            CP_COMMIT();                                                          \
        } while (0)

        if (ng > 0) ISSUE_CP(g * 64, 0);
        if (ng > 1) ISSUE_CP((4 + g) * 64, 1);

        for (int r = 0; r < ng; r++) {
            const int cur = r & 1;
            const int kbase = (4 * r + g) * 64;
            uint32_t* kst = sbuf + gbase + cur * 4608;
            const uint32_t vbytes = smem0 + (gbase + cur * 4608 + 2304) * 4;

            if (r + 1 < ng) CP_WAIT1(); else CP_WAIT0();
            GROUP_BAR(g);

            float s[8][4];
            #pragma unroll
            for (int nk = 0; nk < 8; nk++)
                #pragma unroll
                for (int j2 = 0; j2 < 4; j2++) s[nk][j2] = 0.f;

            #pragma unroll
            for (int c = 0; c < 4; c++) {
                uint32_t bfr[8][2];
                #pragma unroll
                for (int nk = 0; nk < 8; nk++) {
                    const uint32_t* kr = kst + (nk * 8 + gq) * 36 + c * 8 + tg;
                    bfr[nk][0] = kr[0];
                    bfr[nk][1] = kr[4];
                }
                #pragma unroll
                for (int nk = 0; nk < 8; nk++) mma_f16(s[nk], qh2[c], bfr[nk]);
                #pragma unroll
                for (int nk = 0; nk < 8; nk++) mma_f16(s[nk], ql2[c], bfr[nk]);
            }

            if (kbase == qbase) {
                const int row0 = r0l, row1 = r0l + 8;
                #pragma unroll
                for (int nk = 0; nk < 8; nk++) {
                    int c = nk * 8 + tg * 2;
                    if (c     > row0) s[nk][0] = -1e30f;
                    if (c + 1 > row0) s[nk][1] = -1e30f;
                    if (c     > row1) s[nk][2] = -1e30f;
                    if (c + 1 > row1) s[nk][3] = -1e30f;
                }
            }

            float rm0 = -1e30f, rm1 = -1e30f;
            #pragma unroll
            for (int nk = 0; nk < 8; nk++) {
                rm0 = fmaxf(rm0, fmaxf(s[nk][0], s[nk][1]));
                rm1 = fmaxf(rm1, fmaxf(s[nk][2], s[nk][3]));
            }
            rm0 = fmaxf(rm0, __shfl_xor_sync(0xffffffffu, rm0, 1));
            rm0 = fmaxf(rm0, __shfl_xor_sync(0xffffffffu, rm0, 2));
            rm1 = fmaxf(rm1, __shfl_xor_sync(0xffffffffu, rm1, 1));
            rm1 = fmaxf(rm1, __shfl_xor_sync(0xffffffffu, rm1, 2));

            float mn0 = fmaxf(m0, rm0), mn1 = fmaxf(m1, rm1);
            float a0 = exp2f(m0 - mn0), a1 = exp2f(m1 - mn1);
            m0 = mn0; m1 = mn1;
            lacc[0] *= a0; lacc[1] *= a0; lacc[2] *= a1; lacc[3] *= a1;
            #pragma unroll
            for (int nh = 0; nh < 8; nh++) {
                O[nh][0] *= a0; O[nh][1] *= a0;
                O[nh][2] *= a1; O[nh][3] *= a1;
            }

            const uint32_t ones2[2] = {0x3C003C00u, 0x3C003C00u};
            #pragma unroll
            for (int c = 0; c < 4; c++) {
                uint32_t pa[4];
                pa[0] = ex2h2(packh2(s[2 * c][0]     - m0, s[2 * c][1]     - m0));
                pa[1] = ex2h2(packh2(s[2 * c][2]     - m1, s[2 * c][3]     - m1));
                pa[2] = ex2h2(packh2(s[2 * c + 1][0] - m0, s[2 * c + 1][1] - m0));
                pa[3] = ex2h2(packh2(s[2 * c + 1][2] - m1, s[2 * c + 1][3] - m1));
                #pragma unroll
                for (int hb = 0; hb < 4; hb++) {
                    uint32_t d0, d1, d2, d3;
                    uint32_t addr = vbytes + vlane + (uint32_t)(c * 16 * 144 + hb * 32);
                    LDSM4T(d0, d1, d2, d3, addr);
                    uint32_t vb0[2] = {d0, d1};
                    uint32_t vb1[2] = {d2, d3};
                    mma_f16(O[2 * hb],     pa, vb0);
                    mma_f16(O[2 * hb + 1], pa, vb1);
                }
                mma_f16(lacc, pa, ones2);
            }

            GROUP_BAR(g);
            if (r + 2 < ng) ISSUE_CP((4 * (r + 2) + g) * 64, cur);
        }

        float l0 = lacc[0], l1 = lacc[2];

        __syncthreads();
        #pragma unroll
        for (int rr = 1; rr < 4; rr++) {
            if (g == rr) {
                mlb[r0l * 2]           = m0;
                mlb[r0l * 2 + 1]       = l0;
                mlb[(r0l + 8) * 2]     = m1;
                mlb[(r0l + 8) * 2 + 1] = l1;
                #pragma unroll
                for (int nh = 0; nh < 8; nh++) {
                    int c = nh * 8 + tg * 2;
                    *(float2*)&obuf[r0l * 68 + c]       = make_float2(O[nh][0], O[nh][1]);
                    *(float2*)&obuf[(r0l + 8) * 68 + c] = make_float2(O[nh][2], O[nh][3]);
                }
            }
            __syncthreads();
            if (g == 0) {
                float mb0 = mlb[r0l * 2],       lb0 = mlb[r0l * 2 + 1];
                float mb1 = mlb[(r0l + 8) * 2], lb1 = mlb[(r0l + 8) * 2 + 1];
                float M0 = fmaxf(m0, mb0), M1 = fmaxf(m1, mb1);
                float ea0 = exp2f(m0 - M0),  eb0 = exp2f(mb0 - M0);
                float ea1 = exp2f(m1 - M1),  eb1 = exp2f(mb1 - M1);
                l0 = l0 * ea0 + lb0 * eb0;
                l1 = l1 * ea1 + lb1 * eb1;
                m0 = M0; m1 = M1;
                #pragma unroll
                for (int nh = 0; nh < 8; nh++) {
                    int c = nh * 8 + tg * 2;
                    float2 ob0 = *(float2*)&obuf[r0l * 68 + c];
                    float2 ob1 = *(float2*)&obuf[(r0l + 8) * 68 + c];
                    O[nh][0] = O[nh][0] * ea0 + ob0.x * eb0;
                    O[nh][1] = O[nh][1] * ea0 + ob0.y * eb0;
                    O[nh][2] = O[nh][2] * ea1 + ob1.x * eb1;
                    O[nh][3] = O[nh][3] * ea1 + ob1.y * eb1;
                }
            }
            __syncthreads();
        }

        if (g == 0) {
            const float inv0 = 1.f / l0, inv1 = 1.f / l1;
            const int r = qbase + r0l;
            #pragma unroll
            for (int nh = 0; nh < 8; nh++) {
                int c = nh * 8 + tg * 2;
                *(float2*)(out + bOff + (size_t)r * HD + c) =
                    make_float2(O[nh][0] * inv0, O[nh][1] * inv0);
                *(float2*)(out + bOff + (size_t)(r + 8) * HD + c) =
                    make_float2(O[nh][2] * inv1, O[nh][3] * inv1);
            }
        }
        #undef ISSUE_CP
    }
}

// ---------------------------------------------------------------------------
extern "C" void kernel_launch(void* const* d_in, const int* in_sizes, int n_in,
                              void* d_out, int out_size)
{
    const float* x  = (const float*)d_in[0];
    const float* Wq = (const float*)d_in[1];
    const float* bq = (const float*)d_in[2];
    const float* Wk = (const float*)d_in[3];
    const float* bk = (const float*)d_in[4];
    const float* Wv = (const float*)d_in[5];
    const float* bv = (const float*)d_in[6];
    float* out = (float*)d_out;

    cudaFuncSetAttribute(attn_kernel, cudaFuncAttributeMaxDynamicSharedMemorySize, ATTN_SMEM);

    prep_w<<<192, 256>>>(Wq, Wk, Wv);
    qkv_kernel<<<(NB * SEQ) / 64, 256>>>(x, bq, bk, bv);
    attn_kernel<<<dim3(16, NB), 512, ATTN_SMEM>>>(out);
}

// round 13
// speedup vs baseline: 2.1884x; 2.1884x over previous
#include <cuda_runtime.h>
#include <cuda_fp16.h>
#include <cstdint>

#define NB   8
#define SEQ  2048
#define ED   1024
#define HD   64

__device__ float    g_q[NB * SEQ * HD];
__device__ uint32_t g_k16[NB * SEQ * 32];   // fp16x2-packed K
__device__ uint32_t g_v16[NB * SEQ * 32];   // fp16x2-packed V

// ---------------- helpers ----------------
__device__ __forceinline__ void mma_f16(float* d, const uint32_t* a, const uint32_t* b) {
    asm("mma.sync.aligned.m16n8k16.row.col.f32.f16.f16.f32 "
        "{%0,%1,%2,%3}, {%4,%5,%6,%7}, {%8,%9}, {%0,%1,%2,%3};"
        : "+f"(d[0]), "+f"(d[1]), "+f"(d[2]), "+f"(d[3])
        : "r"(a[0]), "r"(a[1]), "r"(a[2]), "r"(a[3]), "r"(b[0]), "r"(b[1]));
}
__device__ __forceinline__ uint32_t packh2(float a, float b) {
    __half2 h = __floats2half2_rn(a, b);
    return *(uint32_t*)&h;
}
__device__ __forceinline__ uint32_t ex2h2(uint32_t in) {
    uint32_t r;
    asm("ex2.approx.f16x2 %0, %1;" : "=r"(r) : "r"(in));
    return r;
}
__device__ __forceinline__ void split2h(float a, float b, uint32_t& hi, uint32_t& lo) {
    __half2 h2 = __floats2half2_rn(a, b);
    float ar = a - __half2float(__low2half(h2));
    float br = b - __half2float(__high2half(h2));
    __half2 l2 = __floats2half2_rn(ar, br);
    hi = *(uint32_t*)&h2;
    lo = *(uint32_t*)&l2;
}

#define CP_ASYNC16(dst, src) \
    asm volatile("cp.async.cg.shared.global [%0], [%1], 16;" :: "r"(dst), "l"(src) : "memory")
#define CP_COMMIT() asm volatile("cp.async.commit_group;" ::: "memory")
#define CP_WAIT1()  asm volatile("cp.async.wait_group 1;" ::: "memory")
#define CP_WAIT0()  asm volatile("cp.async.wait_group 0;" ::: "memory")
#define LDSM4T(d0, d1, d2, d3, a) \
    asm volatile("ldmatrix.sync.aligned.m8n8.x4.trans.shared.b16 {%0,%1,%2,%3}, [%4];" \
                 : "=r"(d0), "=r"(d1), "=r"(d2), "=r"(d3) : "r"(a))

// ---------------------------------------------------------------------------
// QKV via fp16 m16n8k16, 2-term split: q = xh*w + xl*w (x fp16 hi+lo ~22-bit,
// W single fp16, products exact in fp32 accum; dropped-term rel err ~1.4e-4).
// BM=64, N=192, K-chunk 32. 256 CTAs x 8 warps (2m x 4n), 2 CTAs/SM.
// Writes q fp32; k/v packed fp16 in the attn tile layout.
// ---------------------------------------------------------------------------
__global__ __launch_bounds__(256, 2)
void qkv_kernel(const float* __restrict__ x,
                const float* __restrict__ Wq, const float* __restrict__ Wk,
                const float* __restrict__ Wv,
                const float* __restrict__ bq, const float* __restrict__ bk,
                const float* __restrict__ bv)
{
    __shared__ uint32_t xs_h[64][20], xs_l[64][20];
    __shared__ uint32_t ws[192][20];

    const int t    = threadIdx.x;
    const int lane = t & 31;
    const int wid  = t >> 5;
    const int wm   = wid & 1;       // 32-row half
    const int wn   = wid >> 1;      // 48-col slice
    const int gq   = lane >> 2;
    const int tg   = lane & 3;
    const size_t rowBase = (size_t)blockIdx.x * 64;

    float acc[2][6][4];
    #pragma unroll
    for (int mi = 0; mi < 2; mi++)
        #pragma unroll
        for (int ni = 0; ni < 6; ni++)
            #pragma unroll
            for (int j = 0; j < 4; j++) acc[mi][ni][j] = 0.f;

    const int xr  = t >> 2;          // x loader row
    const int xcq = t & 3;           // x loader col quad (8 floats)
    const int wr0 = t >> 2;          // W loader row within 64-row band
    const int wcq = t & 3;

    for (int ch = 0; ch < 32; ch++) {
        __syncthreads();
        // x tile: 8 floats/thread -> fp16 hi/lo packed
        {
            const float* xp = x + (rowBase + xr) * ED + ch * 32 + xcq * 8;
            float4 f0 = *(const float4*)xp;
            float4 f1 = *(const float4*)(xp + 4);
            uint4 hv, lv;
            split2h(f0.x, f0.y, hv.x, lv.x);
            split2h(f0.z, f0.w, hv.y, lv.y);
            split2h(f1.x, f1.y, hv.z, lv.z);
            split2h(f1.z, f1.w, hv.w, lv.w);
            *(uint4*)&xs_h[xr][xcq * 4] = hv;
            *(uint4*)&xs_l[xr][xcq * 4] = lv;
        }
        // W tiles: fp32 load + single-fp16 pack (i=0:Wq, 1:Wk, 2:Wv)
        #pragma unroll
        for (int i = 0; i < 3; i++) {
            const float* src = (i == 0) ? Wq : (i == 1) ? Wk : Wv;
            const float* wp = src + (size_t)wr0 * ED + ch * 32 + wcq * 8;
            float4 f0 = *(const float4*)wp;
            float4 f1 = *(const float4*)(wp + 4);
            uint4 hv;
            hv.x = packh2(f0.x, f0.y);
            hv.y = packh2(f0.z, f0.w);
            hv.z = packh2(f1.x, f1.y);
            hv.w = packh2(f1.z, f1.w);
            *(uint4*)&ws[wr0 + i * 64][wcq * 4] = hv;
        }
        __syncthreads();

        #pragma unroll
        for (int kk = 0; kk < 2; kk++) {
            const int c0 = kk * 8 + tg;
            uint32_t ah[2][4], al[2][4];
            #pragma unroll
            for (int mi = 0; mi < 2; mi++) {
                int r0 = wm * 32 + mi * 16 + gq;
                ah[mi][0] = xs_h[r0][c0];     ah[mi][1] = xs_h[r0 + 8][c0];
                ah[mi][2] = xs_h[r0][c0 + 4]; ah[mi][3] = xs_h[r0 + 8][c0 + 4];
                al[mi][0] = xs_l[r0][c0];     al[mi][1] = xs_l[r0 + 8][c0];
                al[mi][2] = xs_l[r0][c0 + 4]; al[mi][3] = xs_l[r0 + 8][c0 + 4];
            }
            uint32_t bh[6][2];
            #pragma unroll
            for (int ni = 0; ni < 6; ni++) {
                int n0 = wn * 48 + ni * 8 + gq;
                bh[ni][0] = ws[n0][c0];
                bh[ni][1] = ws[n0][c0 + 4];
            }
            #pragma unroll
            for (int mi = 0; mi < 2; mi++)
                #pragma unroll
                for (int ni = 0; ni < 6; ni++) mma_f16(acc[mi][ni], ah[mi], bh[ni]);
            #pragma unroll
            for (int mi = 0; mi < 2; mi++)
                #pragma unroll
                for (int ni = 0; ni < 6; ni++) mma_f16(acc[mi][ni], al[mi], bh[ni]);
        }
    }

    #pragma unroll
    for (int ni = 0; ni < 6; ni++) {
        const int gc0 = wn * 48 + ni * 8;
        const int wi  = gc0 >> 6;
        const int h0  = (gc0 & 63) + tg * 2;
        const float* bp = (wi == 0) ? bq : (wi == 1) ? bk : bv;
        const float b0 = bp[h0], b1 = bp[h0 + 1];
        #pragma unroll
        for (int mi = 0; mi < 2; mi++) {
            size_t r = rowBase + wm * 32 + mi * 16 + gq;
            float v0 = acc[mi][ni][0] + b0, v1 = acc[mi][ni][1] + b1;
            float v2 = acc[mi][ni][2] + b0, v3 = acc[mi][ni][3] + b1;
            if (wi == 0) {
                *(float2*)(g_q + r * HD + h0)       = make_float2(v0, v1);
                *(float2*)(g_q + (r + 8) * HD + h0) = make_float2(v2, v3);
            } else {
                uint32_t* outp = (wi == 1) ? g_k16 : g_v16;
                int hp = ((gc0 & 63) >> 1) + tg;
                outp[r * 32 + hp]       = packh2(v0, v1);
                outp[(r + 8) * 32 + hp] = packh2(v2, v3);
            }
        }
    }
}

// ---------------------------------------------------------------------------
// Causal flash attention v6 (round-10 version, verified at 34us).
// 512 threads = 4 k-split groups x 4 warps, BK=64 tiles, cp.async
// double-buffered fp16 K/V, ldmatrix.trans V fragments, ex2.f16x2 softmax,
// ones-MMA row sums, 4-way analytic merge.
// ---------------------------------------------------------------------------
#define GROUP_BAR(gid) asm volatile("bar.sync %0, 128;" :: "r"((gid) + 1) : "memory")
#define ATTN_SMEM (147456)

extern __shared__ uint32_t sbuf[];

__global__ __launch_bounds__(512, 1)
void attn_kernel(float* __restrict__ out)
{
    const int t    = threadIdx.x;
    const int lane = t & 31;
    const int wid  = t >> 5;
    const int g    = wid >> 2;
    const int qb   = wid & 3;
    const int gq   = lane >> 2;
    const int tg   = lane & 3;
    const int tl   = t & 127;
    const int b    = blockIdx.y;
    const size_t bOff  = (size_t)b * SEQ * HD;
    const size_t bOffH = (size_t)b * SEQ * 32;

    const uint32_t gbase = g * 9216;
    const uint32_t smem0 = (uint32_t)__cvta_generic_to_shared(sbuf);
    float* obuf = (float*)sbuf;
    float* mlb  = (float*)(sbuf + 4352);

    const uint32_t vlane = (uint32_t)(((lane & 7) + ((lane >> 3) & 1) * 8) * 144
                                      + (lane >> 4) * 16);

    const float SC2 = 0.18033688f;     // log2(e) / 8

    for (int pass = 0; pass < 2; pass++) {
        __syncthreads();
        const int qt = pass ? (31 - blockIdx.x) : blockIdx.x;
        const int qbase = qt * 64;
        const int r0l = qb * 16 + gq;

        uint32_t qh2[4][4], ql2[4][4];
        {
            const float* qp = g_q + bOff + (size_t)(qbase + r0l) * HD;
            #pragma unroll
            for (int c = 0; c < 4; c++) {
                int c0 = c * 16 + tg * 2;
                float2 f00 = *(const float2*)(qp + c0);
                float2 f10 = *(const float2*)(qp + 8 * HD + c0);
                float2 f01 = *(const float2*)(qp + c0 + 8);
                float2 f11 = *(const float2*)(qp + 8 * HD + c0 + 8);
                split2h(f00.x * SC2, f00.y * SC2, qh2[c][0], ql2[c][0]);
                split2h(f10.x * SC2, f10.y * SC2, qh2[c][1], ql2[c][1]);
                split2h(f01.x * SC2, f01.y * SC2, qh2[c][2], ql2[c][2]);
                split2h(f11.x * SC2, f11.y * SC2, qh2[c][3], ql2[c][3]);
            }
        }

        float m0 = -1e30f, m1 = -1e30f;
        float lacc[4] = {0.f, 0.f, 0.f, 0.f};
        float O[8][4];
        #pragma unroll
        for (int nh = 0; nh < 8; nh++)
            #pragma unroll
            for (int j = 0; j < 4; j++) O[nh][j] = 0.f;

        const int ng = (qt >= g) ? (((qt - g) >> 2) + 1) : 0;

        #define ISSUE_CP(KB, BUFI) do {                                           \
            uint32_t dstK = smem0 + (gbase + (BUFI) * 4608) * 4;                  \
            uint32_t dstV = dstK + 9216;                                          \
            _Pragma("unroll")                                                     \
            for (int i = 0; i < 4; i++) {                                         \
                int idx = tl + 128 * i;                                           \
                int row = idx >> 3, c = idx & 7;                                  \
                uint32_t so = (uint32_t)(row * 144 + c * 16);                     \
                const uint32_t* sk = g_k16 + bOffH + (size_t)((KB) + row) * 32 + c * 4; \
                const uint32_t* sv = g_v16 + bOffH + (size_t)((KB) + row) * 32 + c * 4; \
                CP_ASYNC16(dstK + so, sk);                                        \
                CP_ASYNC16(dstV + so, sv);                                        \
            }                                                                     \
            CP_COMMIT();                                                          \
        } while (0)

        if (ng > 0) ISSUE_CP(g * 64, 0);
        if (ng > 1) ISSUE_CP((4 + g) * 64, 1);

        for (int r = 0; r < ng; r++) {
            const int cur = r & 1;
            const int kbase = (4 * r + g) * 64;
            uint32_t* kst = sbuf + gbase + cur * 4608;
            const uint32_t vbytes = smem0 + (gbase + cur * 4608 + 2304) * 4;

            if (r + 1 < ng) CP_WAIT1(); else CP_WAIT0();
            GROUP_BAR(g);

            float s[8][4];
            #pragma unroll
            for (int nk = 0; nk < 8; nk++)
                #pragma unroll
                for (int j2 = 0; j2 < 4; j2++) s[nk][j2] = 0.f;

            #pragma unroll
            for (int c = 0; c < 4; c++) {
                uint32_t bfr[8][2];
                #pragma unroll
                for (int nk = 0; nk < 8; nk++) {
                    const uint32_t* kr = kst + (nk * 8 + gq) * 36 + c * 8 + tg;
                    bfr[nk][0] = kr[0];
                    bfr[nk][1] = kr[4];
                }
                #pragma unroll
                for (int nk = 0; nk < 8; nk++) mma_f16(s[nk], qh2[c], bfr[nk]);
                #pragma unroll
                for (int nk = 0; nk < 8; nk++) mma_f16(s[nk], ql2[c], bfr[nk]);
            }

            if (kbase == qbase) {
                const int row0 = r0l, row1 = r0l + 8;
                #pragma unroll
                for (int nk = 0; nk < 8; nk++) {
                    int c = nk * 8 + tg * 2;
                    if (c     > row0) s[nk][0] = -1e30f;
                    if (c + 1 > row0) s[nk][1] = -1e30f;
                    if (c     > row1) s[nk][2] = -1e30f;
                    if (c + 1 > row1) s[nk][3] = -1e30f;
                }
            }

            float rm0 = -1e30f, rm1 = -1e30f;
            #pragma unroll
            for (int nk = 0; nk < 8; nk++) {
                rm0 = fmaxf(rm0, fmaxf(s[nk][0], s[nk][1]));
                rm1 = fmaxf(rm1, fmaxf(s[nk][2], s[nk][3]));
            }
            rm0 = fmaxf(rm0, __shfl_xor_sync(0xffffffffu, rm0, 1));
            rm0 = fmaxf(rm0, __shfl_xor_sync(0xffffffffu, rm0, 2));
            rm1 = fmaxf(rm1, __shfl_xor_sync(0xffffffffu, rm1, 1));
            rm1 = fmaxf(rm1, __shfl_xor_sync(0xffffffffu, rm1, 2));

            float mn0 = fmaxf(m0, rm0), mn1 = fmaxf(m1, rm1);
            float a0 = exp2f(m0 - mn0), a1 = exp2f(m1 - mn1);
            m0 = mn0; m1 = mn1;
            lacc[0] *= a0; lacc[1] *= a0; lacc[2] *= a1; lacc[3] *= a1;
            #pragma unroll
            for (int nh = 0; nh < 8; nh++) {
                O[nh][0] *= a0; O[nh][1] *= a0;
                O[nh][2] *= a1; O[nh][3] *= a1;
            }

            const uint32_t ones2[2] = {0x3C003C00u, 0x3C003C00u};
            #pragma unroll
            for (int c = 0; c < 4; c++) {
                uint32_t pa[4];
                pa[0] = ex2h2(packh2(s[2 * c][0]     - m0, s[2 * c][1]     - m0));
                pa[1] = ex2h2(packh2(s[2 * c][2]     - m1, s[2 * c][3]     - m1));
                pa[2] = ex2h2(packh2(s[2 * c + 1][0] - m0, s[2 * c + 1][1] - m0));
                pa[3] = ex2h2(packh2(s[2 * c + 1][2] - m1, s[2 * c + 1][3] - m1));
                #pragma unroll
                for (int hb = 0; hb < 4; hb++) {
                    uint32_t d0, d1, d2, d3;
                    uint32_t addr = vbytes + vlane + (uint32_t)(c * 16 * 144 + hb * 32);
                    LDSM4T(d0, d1, d2, d3, addr);
                    uint32_t vb0[2] = {d0, d1};
                    uint32_t vb1[2] = {d2, d3};
                    mma_f16(O[2 * hb],     pa, vb0);
                    mma_f16(O[2 * hb + 1], pa, vb1);
                }
                mma_f16(lacc, pa, ones2);
            }

            GROUP_BAR(g);
            if (r + 2 < ng) ISSUE_CP((4 * (r + 2) + g) * 64, cur);
        }

        float l0 = lacc[0], l1 = lacc[2];

        __syncthreads();
        #pragma unroll
        for (int rr = 1; rr < 4; rr++) {
            if (g == rr) {
                mlb[r0l * 2]           = m0;
                mlb[r0l * 2 + 1]       = l0;
                mlb[(r0l + 8) * 2]     = m1;
                mlb[(r0l + 8) * 2 + 1] = l1;
                #pragma unroll
                for (int nh = 0; nh < 8; nh++) {
                    int c = nh * 8 + tg * 2;
                    *(float2*)&obuf[r0l * 68 + c]       = make_float2(O[nh][0], O[nh][1]);
                    *(float2*)&obuf[(r0l + 8) * 68 + c] = make_float2(O[nh][2], O[nh][3]);
                }
            }
            __syncthreads();
            if (g == 0) {
                float mb0 = mlb[r0l * 2],       lb0 = mlb[r0l * 2 + 1];
                float mb1 = mlb[(r0l + 8) * 2], lb1 = mlb[(r0l + 8) * 2 + 1];
                float M0 = fmaxf(m0, mb0), M1 = fmaxf(m1, mb1);
                float ea0 = exp2f(m0 - M0),  eb0 = exp2f(mb0 - M0);
                float ea1 = exp2f(m1 - M1),  eb1 = exp2f(mb1 - M1);
                l0 = l0 * ea0 + lb0 * eb0;
                l1 = l1 * ea1 + lb1 * eb1;
                m0 = M0; m1 = M1;
                #pragma unroll
                for (int nh = 0; nh < 8; nh++) {
                    int c = nh * 8 + tg * 2;
                    float2 ob0 = *(float2*)&obuf[r0l * 68 + c];
                    float2 ob1 = *(float2*)&obuf[(r0l + 8) * 68 + c];
                    O[nh][0] = O[nh][0] * ea0 + ob0.x * eb0;
                    O[nh][1] = O[nh][1] * ea0 + ob0.y * eb0;
                    O[nh][2] = O[nh][2] * ea1 + ob1.x * eb1;
                    O[nh][3] = O[nh][3] * ea1 + ob1.y * eb1;
                }
            }
            __syncthreads();
        }

        if (g == 0) {
            const float inv0 = 1.f / l0, inv1 = 1.f / l1;
            const int r = qbase + r0l;
            #pragma unroll
            for (int nh = 0; nh < 8; nh++) {
                int c = nh * 8 + tg * 2;
                *(float2*)(out + bOff + (size_t)r * HD + c) =
                    make_float2(O[nh][0] * inv0, O[nh][1] * inv0);
                *(float2*)(out + bOff + (size_t)(r + 8) * HD + c) =
                    make_float2(O[nh][2] * inv1, O[nh][3] * inv1);
            }
        }
        #undef ISSUE_CP
    }
}

// ---------------------------------------------------------------------------
extern "C" void kernel_launch(void* const* d_in, const int* in_sizes, int n_in,
                              void* d_out, int out_size)
{
    const float* x  = (const float*)d_in[0];
    const float* Wq = (const float*)d_in[1];
    const float* bq = (const float*)d_in[2];
    const float* Wk = (const float*)d_in[3];
    const float* bk = (const float*)d_in[4];
    const float* Wv = (const float*)d_in[5];
    const float* bv = (const float*)d_in[6];
    float* out = (float*)d_out;

    cudaFuncSetAttribute(attn_kernel, cudaFuncAttributeMaxDynamicSharedMemorySize, ATTN_SMEM);

    qkv_kernel<<<(NB * SEQ) / 64, 256>>>(x, Wq, Wk, Wv, bq, bk, bv);
    attn_kernel<<<dim3(16, NB), 512, ATTN_SMEM>>>(out);
}

// round 14
// speedup vs baseline: 2.5155x; 1.1495x over previous
#include <cuda_runtime.h>
#include <cuda_fp16.h>
#include <cstdint>

#define NB   8
#define SEQ  2048
#define ED   1024
#define HD   64

__device__ float    g_q[NB * SEQ * HD];
__device__ uint32_t g_k16[NB * SEQ * 32];   // fp16x2-packed K
__device__ uint32_t g_v16[NB * SEQ * 32];   // fp16x2-packed V
__device__ uint32_t g_w16[192 * 512];       // fp16x2-packed W (q|k|v stacked)

// ---------------- helpers ----------------
__device__ __forceinline__ void mma_f16(float* d, const uint32_t* a, const uint32_t* b) {
    asm("mma.sync.aligned.m16n8k16.row.col.f32.f16.f16.f32 "
        "{%0,%1,%2,%3}, {%4,%5,%6,%7}, {%8,%9}, {%0,%1,%2,%3};"
        : "+f"(d[0]), "+f"(d[1]), "+f"(d[2]), "+f"(d[3])
        : "r"(a[0]), "r"(a[1]), "r"(a[2]), "r"(a[3]), "r"(b[0]), "r"(b[1]));
}
__device__ __forceinline__ uint32_t packh2(float a, float b) {
    __half2 h = __floats2half2_rn(a, b);
    return *(uint32_t*)&h;
}
__device__ __forceinline__ uint32_t ex2h2(uint32_t in) {
    uint32_t r;
    asm("ex2.approx.f16x2 %0, %1;" : "=r"(r) : "r"(in));
    return r;
}
__device__ __forceinline__ void split2h(float a, float b, uint32_t& hi, uint32_t& lo) {
    __half2 h2 = __floats2half2_rn(a, b);
    float ar = a - __half2float(__low2half(h2));
    float br = b - __half2float(__high2half(h2));
    __half2 l2 = __floats2half2_rn(ar, br);
    hi = *(uint32_t*)&h2;
    lo = *(uint32_t*)&l2;
}

#define CP_ASYNC16(dst, src) \
    asm volatile("cp.async.cg.shared.global [%0], [%1], 16;" :: "r"(dst), "l"(src) : "memory")
#define CP_COMMIT() asm volatile("cp.async.commit_group;" ::: "memory")
#define CP_WAIT1()  asm volatile("cp.async.wait_group 1;" ::: "memory")
#define CP_WAIT0()  asm volatile("cp.async.wait_group 0;" ::: "memory")
#define LDSM4T(d0, d1, d2, d3, a) \
    asm volatile("ldmatrix.sync.aligned.m8n8.x4.trans.shared.b16 {%0,%1,%2,%3}, [%4];" \
                 : "=r"(d0), "=r"(d1), "=r"(d2), "=r"(d3) : "r"(a))

extern __shared__ uint32_t sbuf[];

// ---------------------------------------------------------------------------
// Prep: pack W (q|k|v stacked, 192 x 1024 fp32) into fp16 pairs.
// ---------------------------------------------------------------------------
__global__ void prep_w(const float* __restrict__ Wq, const float* __restrict__ Wk,
                       const float* __restrict__ Wv)
{
    int idx = blockIdx.x * 256 + threadIdx.x;    // 49152 float4 slots
    int row = idx >> 8;
    int f4  = idx & 255;
    const float* src = (row < 64)  ? Wq + (size_t)row * ED
                     : (row < 128) ? Wk + (size_t)(row - 64) * ED
                                   : Wv + (size_t)(row - 128) * ED;
    float4 f = *(const float4*)(src + f4 * 4);
    g_w16[row * 512 + f4 * 2]     = packh2(f.x, f.y);
    g_w16[row * 512 + f4 * 2 + 1] = packh2(f.z, f.w);
}

// ---------------------------------------------------------------------------
// QKV v2: fp16 m16n8k16, 2-term split (xh*w + xl*w), fully cp.async-pipelined.
// x staged raw fp32 (split at fragment-load time); W streamed pre-packed fp16.
// BM=64, N=192, K-chunk 32, double-buffered, 2 CTAs/SM.
// smem (u32): xstage[2][64*40] fp32 at 0; ws[2][192*20] at 5120.
// ---------------------------------------------------------------------------
#define QKV_SMEM (51200)

__global__ __launch_bounds__(256, 2)
void qkv_kernel(const float* __restrict__ x,
                const float* __restrict__ bq, const float* __restrict__ bk,
                const float* __restrict__ bv)
{
    const int t    = threadIdx.x;
    const int lane = t & 31;
    const int wid  = t >> 5;
    const int wm   = wid & 1;       // 32-row half
    const int wn   = wid >> 1;      // 48-col slice
    const int gq   = lane >> 2;
    const int tg   = lane & 3;
    const size_t rowBase = (size_t)blockIdx.x * 64;

    const uint32_t smem0 = (uint32_t)__cvta_generic_to_shared(sbuf);

    float acc[2][6][4];
    #pragma unroll
    for (int mi = 0; mi < 2; mi++)
        #pragma unroll
        for (int ni = 0; ni < 6; ni++)
            #pragma unroll
            for (int j = 0; j < 4; j++) acc[mi][ni][j] = 0.f;

    // issue one chunk's cp.async loads into buffer BUFI
    #define QISSUE(CH, BUFI) do {                                                  \
        uint32_t dstX = smem0 + (BUFI) * 10240;                                    \
        uint32_t dstW = smem0 + 20480 + (BUFI) * 15360;                            \
        _Pragma("unroll")                                                          \
        for (int i = 0; i < 2; i++) {                                              \
            int idx = t + i * 256;                                                 \
            int row = idx >> 3, c8 = idx & 7;                                      \
            CP_ASYNC16(dstX + (uint32_t)(row * 160 + c8 * 16),                     \
                       x + (rowBase + row) * ED + (CH) * 32 + c8 * 4);             \
        }                                                                          \
        _Pragma("unroll")                                                          \
        for (int i = 0; i < 3; i++) {                                              \
            int idx = t + i * 256;                                                 \
            int row = idx >> 2, c4 = (idx & 3) * 4;                                \
            CP_ASYNC16(dstW + (uint32_t)(row * 80 + c4 * 4),                       \
                       g_w16 + (size_t)row * 512 + (CH) * 16 + c4);                \
        }                                                                          \
        CP_COMMIT();                                                               \
    } while (0)

    QISSUE(0, 0);
    QISSUE(1, 1);

    for (int ch = 0; ch < 32; ch++) {
        const int cur = ch & 1;
        if (ch + 1 < 32) CP_WAIT1(); else CP_WAIT0();
        __syncthreads();   // buffer cur complete, visible to all warps

        const float*    xst = (const float*)sbuf + cur * 2560;
        const uint32_t* wst = sbuf + 5120 + cur * 3840;

        #pragma unroll
        for (int kk = 0; kk < 2; kk++) {
            const int c0 = kk * 8 + tg;
            // B fragments (W fp16, stride-20 conflict-free)
            uint32_t bh[6][2];
            #pragma unroll
            for (int ni = 0; ni < 6; ni++) {
                int n0 = wn * 48 + ni * 8 + gq;
                bh[ni][0] = wst[n0 * 20 + c0];
                bh[ni][1] = wst[n0 * 20 + c0 + 4];
            }
            // A fragments: read fp32 pairs, split hi/lo at use
            uint32_t ah[2][4], al[2][4];
            const int col = kk * 16 + tg * 2;
            #pragma unroll
            for (int mi = 0; mi < 2; mi++) {
                int r0 = wm * 32 + mi * 16 + gq;
                float2 f00 = *(const float2*)&xst[r0 * 40 + col];
                float2 f10 = *(const float2*)&xst[(r0 + 8) * 40 + col];
                float2 f01 = *(const float2*)&xst[r0 * 40 + col + 8];
                float2 f11 = *(const float2*)&xst[(r0 + 8) * 40 + col + 8];
                split2h(f00.x, f00.y, ah[mi][0], al[mi][0]);
                split2h(f10.x, f10.y, ah[mi][1], al[mi][1]);
                split2h(f01.x, f01.y, ah[mi][2], al[mi][2]);
                split2h(f11.x, f11.y, ah[mi][3], al[mi][3]);
            }
            #pragma unroll
            for (int mi = 0; mi < 2; mi++)
                #pragma unroll
                for (int ni = 0; ni < 6; ni++) mma_f16(acc[mi][ni], ah[mi], bh[ni]);
            #pragma unroll
            for (int mi = 0; mi < 2; mi++)
                #pragma unroll
                for (int ni = 0; ni < 6; ni++) mma_f16(acc[mi][ni], al[mi], bh[ni]);
        }

        __syncthreads();   // all warps done reading buffer cur
        if (ch + 2 < 32) QISSUE(ch + 2, cur);
    }
    #undef QISSUE

    #pragma unroll
    for (int ni = 0; ni < 6; ni++) {
        const int gc0 = wn * 48 + ni * 8;
        const int wi  = gc0 >> 6;
        const int h0  = (gc0 & 63) + tg * 2;
        const float* bp = (wi == 0) ? bq : (wi == 1) ? bk : bv;
        const float b0 = bp[h0], b1 = bp[h0 + 1];
        #pragma unroll
        for (int mi = 0; mi < 2; mi++) {
            size_t r = rowBase + wm * 32 + mi * 16 + gq;
            float v0 = acc[mi][ni][0] + b0, v1 = acc[mi][ni][1] + b1;
            float v2 = acc[mi][ni][2] + b0, v3 = acc[mi][ni][3] + b1;
            if (wi == 0) {
                *(float2*)(g_q + r * HD + h0)       = make_float2(v0, v1);
                *(float2*)(g_q + (r + 8) * HD + h0) = make_float2(v2, v3);
            } else {
                uint32_t* outp = (wi == 1) ? g_k16 : g_v16;
                int hp = ((gc0 & 63) >> 1) + tg;
                outp[r * 32 + hp]       = packh2(v0, v1);
                outp[(r + 8) * 32 + hp] = packh2(v2, v3);
            }
        }
    }
}

// ---------------------------------------------------------------------------
// Causal flash attention v6 (verified at 34us — unchanged).
// ---------------------------------------------------------------------------
#define GROUP_BAR(gid) asm volatile("bar.sync %0, 128;" :: "r"((gid) + 1) : "memory")
#define ATTN_SMEM (147456)

__global__ __launch_bounds__(512, 1)
void attn_kernel(float* __restrict__ out)
{
    const int t    = threadIdx.x;
    const int lane = t & 31;
    const int wid  = t >> 5;
    const int g    = wid >> 2;
    const int qb   = wid & 3;
    const int gq   = lane >> 2;
    const int tg   = lane & 3;
    const int tl   = t & 127;
    const int b    = blockIdx.y;
    const size_t bOff  = (size_t)b * SEQ * HD;
    const size_t bOffH = (size_t)b * SEQ * 32;

    const uint32_t gbase = g * 9216;
    const uint32_t smem0 = (uint32_t)__cvta_generic_to_shared(sbuf);
    float* obuf = (float*)sbuf;
    float* mlb  = (float*)(sbuf + 4352);

    const uint32_t vlane = (uint32_t)(((lane & 7) + ((lane >> 3) & 1) * 8) * 144
                                      + (lane >> 4) * 16);

    const float SC2 = 0.18033688f;     // log2(e) / 8

    for (int pass = 0; pass < 2; pass++) {
        __syncthreads();
        const int qt = pass ? (31 - blockIdx.x) : blockIdx.x;
        const int qbase = qt * 64;
        const int r0l = qb * 16 + gq;

        uint32_t qh2[4][4], ql2[4][4];
        {
            const float* qp = g_q + bOff + (size_t)(qbase + r0l) * HD;
            #pragma unroll
            for (int c = 0; c < 4; c++) {
                int c0 = c * 16 + tg * 2;
                float2 f00 = *(const float2*)(qp + c0);
                float2 f10 = *(const float2*)(qp + 8 * HD + c0);
                float2 f01 = *(const float2*)(qp + c0 + 8);
                float2 f11 = *(const float2*)(qp + 8 * HD + c0 + 8);
                split2h(f00.x * SC2, f00.y * SC2, qh2[c][0], ql2[c][0]);
                split2h(f10.x * SC2, f10.y * SC2, qh2[c][1], ql2[c][1]);
                split2h(f01.x * SC2, f01.y * SC2, qh2[c][2], ql2[c][2]);
                split2h(f11.x * SC2, f11.y * SC2, qh2[c][3], ql2[c][3]);
            }
        }

        float m0 = -1e30f, m1 = -1e30f;
        float lacc[4] = {0.f, 0.f, 0.f, 0.f};
        float O[8][4];
        #pragma unroll
        for (int nh = 0; nh < 8; nh++)
            #pragma unroll
            for (int j = 0; j < 4; j++) O[nh][j] = 0.f;

        const int ng = (qt >= g) ? (((qt - g) >> 2) + 1) : 0;

        #define ISSUE_CP(KB, BUFI) do {                                           \
            uint32_t dstK = smem0 + (gbase + (BUFI) * 4608) * 4;                  \
            uint32_t dstV = dstK + 9216;                                          \
            _Pragma("unroll")                                                     \
            for (int i = 0; i < 4; i++) {                                         \
                int idx = tl + 128 * i;                                           \
                int row = idx >> 3, c = idx & 7;                                  \
                uint32_t so = (uint32_t)(row * 144 + c * 16);                     \
                const uint32_t* sk = g_k16 + bOffH + (size_t)((KB) + row) * 32 + c * 4; \
                const uint32_t* sv = g_v16 + bOffH + (size_t)((KB) + row) * 32 + c * 4; \
                CP_ASYNC16(dstK + so, sk);                                        \
                CP_ASYNC16(dstV + so, sv);                                        \
            }                                                                     \
            CP_COMMIT();                                                          \
        } while (0)

        if (ng > 0) ISSUE_CP(g * 64, 0);
        if (ng > 1) ISSUE_CP((4 + g) * 64, 1);

        for (int r = 0; r < ng; r++) {
            const int cur = r & 1;
            const int kbase = (4 * r + g) * 64;
            uint32_t* kst = sbuf + gbase + cur * 4608;
            const uint32_t vbytes = smem0 + (gbase + cur * 4608 + 2304) * 4;

            if (r + 1 < ng) CP_WAIT1(); else CP_WAIT0();
            GROUP_BAR(g);

            float s[8][4];
            #pragma unroll
            for (int nk = 0; nk < 8; nk++)
                #pragma unroll
                for (int j2 = 0; j2 < 4; j2++) s[nk][j2] = 0.f;

            #pragma unroll
            for (int c = 0; c < 4; c++) {
                uint32_t bfr[8][2];
                #pragma unroll
                for (int nk = 0; nk < 8; nk++) {
                    const uint32_t* kr = kst + (nk * 8 + gq) * 36 + c * 8 + tg;
                    bfr[nk][0] = kr[0];
                    bfr[nk][1] = kr[4];
                }
                #pragma unroll
                for (int nk = 0; nk < 8; nk++) mma_f16(s[nk], qh2[c], bfr[nk]);
                #pragma unroll
                for (int nk = 0; nk < 8; nk++) mma_f16(s[nk], ql2[c], bfr[nk]);
            }

            if (kbase == qbase) {
                const int row0 = r0l, row1 = r0l + 8;
                #pragma unroll
                for (int nk = 0; nk < 8; nk++) {
                    int c = nk * 8 + tg * 2;
                    if (c     > row0) s[nk][0] = -1e30f;
                    if (c + 1 > row0) s[nk][1] = -1e30f;
                    if (c     > row1) s[nk][2] = -1e30f;
                    if (c + 1 > row1) s[nk][3] = -1e30f;
                }
            }

            float rm0 = -1e30f, rm1 = -1e30f;
            #pragma unroll
            for (int nk = 0; nk < 8; nk++) {
                rm0 = fmaxf(rm0, fmaxf(s[nk][0], s[nk][1]));
                rm1 = fmaxf(rm1, fmaxf(s[nk][2], s[nk][3]));
            }
            rm0 = fmaxf(rm0, __shfl_xor_sync(0xffffffffu, rm0, 1));
            rm0 = fmaxf(rm0, __shfl_xor_sync(0xffffffffu, rm0, 2));
            rm1 = fmaxf(rm1, __shfl_xor_sync(0xffffffffu, rm1, 1));
            rm1 = fmaxf(rm1, __shfl_xor_sync(0xffffffffu, rm1, 2));

            float mn0 = fmaxf(m0, rm0), mn1 = fmaxf(m1, rm1);
            float a0 = exp2f(m0 - mn0), a1 = exp2f(m1 - mn1);
            m0 = mn0; m1 = mn1;
            lacc[0] *= a0; lacc[1] *= a0; lacc[2] *= a1; lacc[3] *= a1;
            #pragma unroll
            for (int nh = 0; nh < 8; nh++) {
                O[nh][0] *= a0; O[nh][1] *= a0;
                O[nh][2] *= a1; O[nh][3] *= a1;
            }

            const uint32_t ones2[2] = {0x3C003C00u, 0x3C003C00u};
            #pragma unroll
            for (int c = 0; c < 4; c++) {
                uint32_t pa[4];
                pa[0] = ex2h2(packh2(s[2 * c][0]     - m0, s[2 * c][1]     - m0));
                pa[1] = ex2h2(packh2(s[2 * c][2]     - m1, s[2 * c][3]     - m1));
                pa[2] = ex2h2(packh2(s[2 * c + 1][0] - m0, s[2 * c + 1][1] - m0));
                pa[3] = ex2h2(packh2(s[2 * c + 1][2] - m1, s[2 * c + 1][3] - m1));
                #pragma unroll
                for (int hb = 0; hb < 4; hb++) {
                    uint32_t d0, d1, d2, d3;
                    uint32_t addr = vbytes + vlane + (uint32_t)(c * 16 * 144 + hb * 32);
                    LDSM4T(d0, d1, d2, d3, addr);
                    uint32_t vb0[2] = {d0, d1};
                    uint32_t vb1[2] = {d2, d3};
                    mma_f16(O[2 * hb],     pa, vb0);
                    mma_f16(O[2 * hb + 1], pa, vb1);
                }
                mma_f16(lacc, pa, ones2);
            }

            GROUP_BAR(g);
            if (r + 2 < ng) ISSUE_CP((4 * (r + 2) + g) * 64, cur);
        }

        float l0 = lacc[0], l1 = lacc[2];

        __syncthreads();
        #pragma unroll
        for (int rr = 1; rr < 4; rr++) {
            if (g == rr) {
                mlb[r0l * 2]           = m0;
                mlb[r0l * 2 + 1]       = l0;
                mlb[(r0l + 8) * 2]     = m1;
                mlb[(r0l + 8) * 2 + 1] = l1;
                #pragma unroll
                for (int nh = 0; nh < 8; nh++) {
                    int c = nh * 8 + tg * 2;
                    *(float2*)&obuf[r0l * 68 + c]       = make_float2(O[nh][0], O[nh][1]);
                    *(float2*)&obuf[(r0l + 8) * 68 + c] = make_float2(O[nh][2], O[nh][3]);
                }
            }
            __syncthreads();
            if (g == 0) {
                float mb0 = mlb[r0l * 2],       lb0 = mlb[r0l * 2 + 1];
                float mb1 = mlb[(r0l + 8) * 2], lb1 = mlb[(r0l + 8) * 2 + 1];
                float M0 = fmaxf(m0, mb0), M1 = fmaxf(m1, mb1);
                float ea0 = exp2f(m0 - M0),  eb0 = exp2f(mb0 - M0);
                float ea1 = exp2f(m1 - M1),  eb1 = exp2f(mb1 - M1);
                l0 = l0 * ea0 + lb0 * eb0;
                l1 = l1 * ea1 + lb1 * eb1;
                m0 = M0; m1 = M1;
                #pragma unroll
                for (int nh = 0; nh < 8; nh++) {
                    int c = nh * 8 + tg * 2;
                    float2 ob0 = *(float2*)&obuf[r0l * 68 + c];
                    float2 ob1 = *(float2*)&obuf[(r0l + 8) * 68 + c];
                    O[nh][0] = O[nh][0] * ea0 + ob0.x * eb0;
                    O[nh][1] = O[nh][1] * ea0 + ob0.y * eb0;
                    O[nh][2] = O[nh][2] * ea1 + ob1.x * eb1;
                    O[nh][3] = O[nh][3] * ea1 + ob1.y * eb1;
                }
            }
            __syncthreads();
        }

        if (g == 0) {
            const float inv0 = 1.f / l0, inv1 = 1.f / l1;
            const int r = qbase + r0l;
            #pragma unroll
            for (int nh = 0; nh < 8; nh++) {
                int c = nh * 8 + tg * 2;
                *(float2*)(out + bOff + (size_t)r * HD + c) =
                    make_float2(O[nh][0] * inv0, O[nh][1] * inv0);
                *(float2*)(out + bOff + (size_t)(r + 8) * HD + c) =
                    make_float2(O[nh][2] * inv1, O[nh][3] * inv1);
            }
        }
        #undef ISSUE_CP
    }
}

// ---------------------------------------------------------------------------
extern "C" void kernel_launch(void* const* d_in, const int* in_sizes, int n_in,
                              void* d_out, int out_size)
{
    const float* x  = (const float*)d_in[0];
    const float* Wq = (const float*)d_in[1];
    const float* bq = (const float*)d_in[2];
    const float* Wk = (const float*)d_in[3];
    const float* bk = (const float*)d_in[4];
    const float* Wv = (const float*)d_in[5];
    const float* bv = (const float*)d_in[6];
    float* out = (float*)d_out;

    cudaFuncSetAttribute(qkv_kernel,  cudaFuncAttributeMaxDynamicSharedMemorySize, QKV_SMEM);
    cudaFuncSetAttribute(attn_kernel, cudaFuncAttributeMaxDynamicSharedMemorySize, ATTN_SMEM);

    prep_w<<<192, 256>>>(Wq, Wk, Wv);
    qkv_kernel<<<(NB * SEQ) / 64, 256, QKV_SMEM>>>(x, bq, bk, bv);
    attn_kernel<<<dim3(16, NB), 512, ATTN_SMEM>>>(out);
}

// round 15
// speedup vs baseline: 2.6087x; 1.0370x over previous
#include <cuda_runtime.h>
#include <cuda_fp16.h>
#include <cstdint>

#define NB   8
#define SEQ  2048
#define ED   1024
#define HD   64

__device__ float    g_q[NB * SEQ * HD];
__device__ uint32_t g_k16[NB * SEQ * 32];   // fp16x2-packed K
__device__ uint32_t g_v16[NB * SEQ * 32];   // fp16x2-packed V
__device__ uint32_t g_w16[192 * 512];       // fp16x2-packed W (q|k|v stacked)

// ---------------- helpers ----------------
__device__ __forceinline__ void mma_f16(float* d, const uint32_t* a, const uint32_t* b) {
    asm("mma.sync.aligned.m16n8k16.row.col.f32.f16.f16.f32 "
        "{%0,%1,%2,%3}, {%4,%5,%6,%7}, {%8,%9}, {%0,%1,%2,%3};"
        : "+f"(d[0]), "+f"(d[1]), "+f"(d[2]), "+f"(d[3])
        : "r"(a[0]), "r"(a[1]), "r"(a[2]), "r"(a[3]), "r"(b[0]), "r"(b[1]));
}
__device__ __forceinline__ uint32_t packh2(float a, float b) {
    __half2 h = __floats2half2_rn(a, b);
    return *(uint32_t*)&h;
}
__device__ __forceinline__ uint32_t ex2h2(uint32_t in) {
    uint32_t r;
    asm("ex2.approx.f16x2 %0, %1;" : "=r"(r) : "r"(in));
    return r;
}
__device__ __forceinline__ void split2h(float a, float b, uint32_t& hi, uint32_t& lo) {
    __half2 h2 = __floats2half2_rn(a, b);
    float ar = a - __half2float(__low2half(h2));
    float br = b - __half2float(__high2half(h2));
    __half2 l2 = __floats2half2_rn(ar, br);
    hi = *(uint32_t*)&h2;
    lo = *(uint32_t*)&l2;
}

#define CP_ASYNC16(dst, src) \
    asm volatile("cp.async.cg.shared.global [%0], [%1], 16;" :: "r"(dst), "l"(src) : "memory")
#define CP_COMMIT() asm volatile("cp.async.commit_group;" ::: "memory")
#define CP_WAIT1()  asm volatile("cp.async.wait_group 1;" ::: "memory")
#define CP_WAIT0()  asm volatile("cp.async.wait_group 0;" ::: "memory")
#define LDSM4T(d0, d1, d2, d3, a) \
    asm volatile("ldmatrix.sync.aligned.m8n8.x4.trans.shared.b16 {%0,%1,%2,%3}, [%4];" \
                 : "=r"(d0), "=r"(d1), "=r"(d2), "=r"(d3) : "r"(a))

extern __shared__ uint32_t sbuf[];

// ---------------------------------------------------------------------------
// Prep: pack W (q|k|v stacked, 192 x 1024 fp32) into fp16 pairs.
// ---------------------------------------------------------------------------
__global__ void prep_w(const float* __restrict__ Wq, const float* __restrict__ Wk,
                       const float* __restrict__ Wv)
{
    int idx = blockIdx.x * 256 + threadIdx.x;
    int row = idx >> 8;
    int f4  = idx & 255;
    const float* src = (row < 64)  ? Wq + (size_t)row * ED
                     : (row < 128) ? Wk + (size_t)(row - 64) * ED
                                   : Wv + (size_t)(row - 128) * ED;
    float4 f = *(const float4*)(src + f4 * 4);
    g_w16[row * 512 + f4 * 2]     = packh2(f.x, f.y);
    g_w16[row * 512 + f4 * 2 + 1] = packh2(f.z, f.w);
}

// ---------------------------------------------------------------------------
// QKV v3: fp16 m16n8k16, mixed precision by destination:
//   q (read back fp32, needs accuracy): xh*w + xl*w (2-term, ~22-bit x)
//   k,v (stored fp16 anyway):            xh*w only (1 term)
// Column blocks interleaved: warp wn owns blocks (wn + ni*4) so each warp
// holds exactly 2 q-blocks -> uniform 16 MMAs/warp/kstep (was 24).
// cp.async double-buffered (x raw fp32, split at fragment-load; W fp16).
// ---------------------------------------------------------------------------
#define QKV_SMEM (51200)

__global__ __launch_bounds__(256, 2)
void qkv_kernel(const float* __restrict__ x,
                const float* __restrict__ bq, const float* __restrict__ bk,
                const float* __restrict__ bv)
{
    const int t    = threadIdx.x;
    const int lane = t & 31;
    const int wid  = t >> 5;
    const int wm   = wid & 1;       // 32-row half
    const int wn   = wid >> 1;      // interleave base
    const int gq   = lane >> 2;
    const int tg   = lane & 3;
    const size_t rowBase = (size_t)blockIdx.x * 64;

    const uint32_t smem0 = (uint32_t)__cvta_generic_to_shared(sbuf);

    float acc[2][6][4];
    #pragma unroll
    for (int mi = 0; mi < 2; mi++)
        #pragma unroll
        for (int ni = 0; ni < 6; ni++)
            #pragma unroll
            for (int j = 0; j < 4; j++) acc[mi][ni][j] = 0.f;

    #define QISSUE(CH, BUFI) do {                                                  \
        uint32_t dstX = smem0 + (BUFI) * 10240;                                    \
        uint32_t dstW = smem0 + 20480 + (BUFI) * 15360;                            \
        _Pragma("unroll")                                                          \
        for (int i = 0; i < 2; i++) {                                              \
            int idx = t + i * 256;                                                 \
            int row = idx >> 3, c8 = idx & 7;                                      \
            CP_ASYNC16(dstX + (uint32_t)(row * 160 + c8 * 16),                     \
                       x + (rowBase + row) * ED + (CH) * 32 + c8 * 4);             \
        }                                                                          \
        _Pragma("unroll")                                                          \
        for (int i = 0; i < 3; i++) {                                              \
            int idx = t + i * 256;                                                 \
            int row = idx >> 2, c4 = (idx & 3) * 4;                                \
            CP_ASYNC16(dstW + (uint32_t)(row * 80 + c4 * 4),                       \
                       g_w16 + (size_t)row * 512 + (CH) * 16 + c4);                \
        }                                                                          \
        CP_COMMIT();                                                               \
    } while (0)

    QISSUE(0, 0);
    QISSUE(1, 1);

    for (int ch = 0; ch < 32; ch++) {
        const int cur = ch & 1;
        if (ch + 1 < 32) CP_WAIT1(); else CP_WAIT0();
        __syncthreads();

        const float*    xst = (const float*)sbuf + cur * 2560;
        const uint32_t* wst = sbuf + 5120 + cur * 3840;

        #pragma unroll
        for (int kk = 0; kk < 2; kk++) {
            const int c0 = kk * 8 + tg;
            // B fragments: interleaved blocks (wn + ni*4)*8
            uint32_t bh[6][2];
            #pragma unroll
            for (int ni = 0; ni < 6; ni++) {
                int n0 = (wn + ni * 4) * 8 + gq;
                bh[ni][0] = wst[n0 * 20 + c0];
                bh[ni][1] = wst[n0 * 20 + c0 + 4];
            }
            // A fragments: fp32 pairs, split hi/lo at use
            uint32_t ah[2][4], al[2][4];
            const int col = kk * 16 + tg * 2;
            #pragma unroll
            for (int mi = 0; mi < 2; mi++) {
                int r0 = wm * 32 + mi * 16 + gq;
                float2 f00 = *(const float2*)&xst[r0 * 40 + col];
                float2 f10 = *(const float2*)&xst[(r0 + 8) * 40 + col];
                float2 f01 = *(const float2*)&xst[r0 * 40 + col + 8];
                float2 f11 = *(const float2*)&xst[(r0 + 8) * 40 + col + 8];
                split2h(f00.x, f00.y, ah[mi][0], al[mi][0]);
                split2h(f10.x, f10.y, ah[mi][1], al[mi][1]);
                split2h(f01.x, f01.y, ah[mi][2], al[mi][2]);
                split2h(f11.x, f11.y, ah[mi][3], al[mi][3]);
            }
            // hi term: all 6 blocks (q, k, v)
            #pragma unroll
            for (int mi = 0; mi < 2; mi++)
                #pragma unroll
                for (int ni = 0; ni < 6; ni++) mma_f16(acc[mi][ni], ah[mi], bh[ni]);
            // lo term: q blocks only (ni = 0, 1 -> cols < 64)
            #pragma unroll
            for (int mi = 0; mi < 2; mi++)
                #pragma unroll
                for (int ni = 0; ni < 2; ni++) mma_f16(acc[mi][ni], al[mi], bh[ni]);
        }

        __syncthreads();
        if (ch + 2 < 32) QISSUE(ch + 2, cur);
    }
    #undef QISSUE

    #pragma unroll
    for (int ni = 0; ni < 6; ni++) {
        const int gc0 = (wn + ni * 4) * 8;
        const int wi  = gc0 >> 6;
        const int h0  = (gc0 & 63) + tg * 2;
        const float* bp = (wi == 0) ? bq : (wi == 1) ? bk : bv;
        const float b0 = bp[h0], b1 = bp[h0 + 1];
        #pragma unroll
        for (int mi = 0; mi < 2; mi++) {
            size_t r = rowBase + wm * 32 + mi * 16 + gq;
            float v0 = acc[mi][ni][0] + b0, v1 = acc[mi][ni][1] + b1;
            float v2 = acc[mi][ni][2] + b0, v3 = acc[mi][ni][3] + b1;
            if (wi == 0) {
                *(float2*)(g_q + r * HD + h0)       = make_float2(v0, v1);
                *(float2*)(g_q + (r + 8) * HD + h0) = make_float2(v2, v3);
            } else {
                uint32_t* outp = (wi == 1) ? g_k16 : g_v16;
                int hp = ((gc0 & 63) >> 1) + tg;
                outp[r * 32 + hp]       = packh2(v0, v1);
                outp[(r + 8) * 32 + hp] = packh2(v2, v3);
            }
        }
    }
}

// ---------------------------------------------------------------------------
// Causal flash attention v6 (verified at 34us — unchanged).
// ---------------------------------------------------------------------------
#define GROUP_BAR(gid) asm volatile("bar.sync %0, 128;" :: "r"((gid) + 1) : "memory")
#define ATTN_SMEM (147456)

__global__ __launch_bounds__(512, 1)
void attn_kernel(float* __restrict__ out)
{
    const int t    = threadIdx.x;
    const int lane = t & 31;
    const int wid  = t >> 5;
    const int g    = wid >> 2;
    const int qb   = wid & 3;
    const int gq   = lane >> 2;
    const int tg   = lane & 3;
    const int tl   = t & 127;
    const int b    = blockIdx.y;
    const size_t bOff  = (size_t)b * SEQ * HD;
    const size_t bOffH = (size_t)b * SEQ * 32;

    const uint32_t gbase = g * 9216;
    const uint32_t smem0 = (uint32_t)__cvta_generic_to_shared(sbuf);
    float* obuf = (float*)sbuf;
    float* mlb  = (float*)(sbuf + 4352);

    const uint32_t vlane = (uint32_t)(((lane & 7) + ((lane >> 3) & 1) * 8) * 144
                                      + (lane >> 4) * 16);

    const float SC2 = 0.18033688f;     // log2(e) / 8

    for (int pass = 0; pass < 2; pass++) {
        __syncthreads();
        const int qt = pass ? (31 - blockIdx.x) : blockIdx.x;
        const int qbase = qt * 64;
        const int r0l = qb * 16 + gq;

        uint32_t qh2[4][4], ql2[4][4];
        {
            const float* qp = g_q + bOff + (size_t)(qbase + r0l) * HD;
            #pragma unroll
            for (int c = 0; c < 4; c++) {
                int c0 = c * 16 + tg * 2;
                float2 f00 = *(const float2*)(qp + c0);
                float2 f10 = *(const float2*)(qp + 8 * HD + c0);
                float2 f01 = *(const float2*)(qp + c0 + 8);
                float2 f11 = *(const float2*)(qp + 8 * HD + c0 + 8);
                split2h(f00.x * SC2, f00.y * SC2, qh2[c][0], ql2[c][0]);
                split2h(f10.x * SC2, f10.y * SC2, qh2[c][1], ql2[c][1]);
                split2h(f01.x * SC2, f01.y * SC2, qh2[c][2], ql2[c][2]);
                split2h(f11.x * SC2, f11.y * SC2, qh2[c][3], ql2[c][3]);
            }
        }

        float m0 = -1e30f, m1 = -1e30f;
        float lacc[4] = {0.f, 0.f, 0.f, 0.f};
        float O[8][4];
        #pragma unroll
        for (int nh = 0; nh < 8; nh++)
            #pragma unroll
            for (int j = 0; j < 4; j++) O[nh][j] = 0.f;

        const int ng = (qt >= g) ? (((qt - g) >> 2) + 1) : 0;

        #define ISSUE_CP(KB, BUFI) do {                                           \
            uint32_t dstK = smem0 + (gbase + (BUFI) * 4608) * 4;                  \
            uint32_t dstV = dstK + 9216;                                          \
            _Pragma("unroll")                                                     \
            for (int i = 0; i < 4; i++) {                                         \
                int idx = tl + 128 * i;                                           \
                int row = idx >> 3, c = idx & 7;                                  \
                uint32_t so = (uint32_t)(row * 144 + c * 16);                     \
                const uint32_t* sk = g_k16 + bOffH + (size_t)((KB) + row) * 32 + c * 4; \
                const uint32_t* sv = g_v16 + bOffH + (size_t)((KB) + row) * 32 + c * 4; \
                CP_ASYNC16(dstK + so, sk);                                        \
                CP_ASYNC16(dstV + so, sv);                                        \
            }                                                                     \
            CP_COMMIT();                                                          \
        } while (0)

        if (ng > 0) ISSUE_CP(g * 64, 0);
        if (ng > 1) ISSUE_CP((4 + g) * 64, 1);

        for (int r = 0; r < ng; r++) {
            const int cur = r & 1;
            const int kbase = (4 * r + g) * 64;
            uint32_t* kst = sbuf + gbase + cur * 4608;
            const uint32_t vbytes = smem0 + (gbase + cur * 4608 + 2304) * 4;

            if (r + 1 < ng) CP_WAIT1(); else CP_WAIT0();
            GROUP_BAR(g);

            float s[8][4];
            #pragma unroll
            for (int nk = 0; nk < 8; nk++)
                #pragma unroll
                for (int j2 = 0; j2 < 4; j2++) s[nk][j2] = 0.f;

            #pragma unroll
            for (int c = 0; c < 4; c++) {
                uint32_t bfr[8][2];
                #pragma unroll
                for (int nk = 0; nk < 8; nk++) {
                    const uint32_t* kr = kst + (nk * 8 + gq) * 36 + c * 8 + tg;
                    bfr[nk][0] = kr[0];
                    bfr[nk][1] = kr[4];
                }
                #pragma unroll
                for (int nk = 0; nk < 8; nk++) mma_f16(s[nk], qh2[c], bfr[nk]);
                #pragma unroll
                for (int nk = 0; nk < 8; nk++) mma_f16(s[nk], ql2[c], bfr[nk]);
            }

            if (kbase == qbase) {
                const int row0 = r0l, row1 = r0l + 8;
                #pragma unroll
                for (int nk = 0; nk < 8; nk++) {
                    int c = nk * 8 + tg * 2;
                    if (c     > row0) s[nk][0] = -1e30f;
                    if (c + 1 > row0) s[nk][1] = -1e30f;
                    if (c     > row1) s[nk][2] = -1e30f;
                    if (c + 1 > row1) s[nk][3] = -1e30f;
                }
            }

            float rm0 = -1e30f, rm1 = -1e30f;
            #pragma unroll
            for (int nk = 0; nk < 8; nk++) {
                rm0 = fmaxf(rm0, fmaxf(s[nk][0], s[nk][1]));
                rm1 = fmaxf(rm1, fmaxf(s[nk][2], s[nk][3]));
            }
            rm0 = fmaxf(rm0, __shfl_xor_sync(0xffffffffu, rm0, 1));
            rm0 = fmaxf(rm0, __shfl_xor_sync(0xffffffffu, rm0, 2));
            rm1 = fmaxf(rm1, __shfl_xor_sync(0xffffffffu, rm1, 1));
            rm1 = fmaxf(rm1, __shfl_xor_sync(0xffffffffu, rm1, 2));

            float mn0 = fmaxf(m0, rm0), mn1 = fmaxf(m1, rm1);
            float a0 = exp2f(m0 - mn0), a1 = exp2f(m1 - mn1);
            m0 = mn0; m1 = mn1;
            lacc[0] *= a0; lacc[1] *= a0; lacc[2] *= a1; lacc[3] *= a1;
            #pragma unroll
            for (int nh = 0; nh < 8; nh++) {
                O[nh][0] *= a0; O[nh][1] *= a0;
                O[nh][2] *= a1; O[nh][3] *= a1;
            }

            const uint32_t ones2[2] = {0x3C003C00u, 0x3C003C00u};
            #pragma unroll
            for (int c = 0; c < 4; c++) {
                uint32_t pa[4];
                pa[0] = ex2h2(packh2(s[2 * c][0]     - m0, s[2 * c][1]     - m0));
                pa[1] = ex2h2(packh2(s[2 * c][2]     - m1, s[2 * c][3]     - m1));
                pa[2] = ex2h2(packh2(s[2 * c + 1][0] - m0, s[2 * c + 1][1] - m0));
                pa[3] = ex2h2(packh2(s[2 * c + 1][2] - m1, s[2 * c + 1][3] - m1));
                #pragma unroll
                for (int hb = 0; hb < 4; hb++) {
                    uint32_t d0, d1, d2, d3;
                    uint32_t addr = vbytes + vlane + (uint32_t)(c * 16 * 144 + hb * 32);
                    LDSM4T(d0, d1, d2, d3, addr);
                    uint32_t vb0[2] = {d0, d1};
                    uint32_t vb1[2] = {d2, d3};
                    mma_f16(O[2 * hb],     pa, vb0);
                    mma_f16(O[2 * hb + 1], pa, vb1);
                }
                mma_f16(lacc, pa, ones2);
            }

            GROUP_BAR(g);
            if (r + 2 < ng) ISSUE_CP((4 * (r + 2) + g) * 64, cur);
        }

        float l0 = lacc[0], l1 = lacc[2];

        __syncthreads();
        #pragma unroll
        for (int rr = 1; rr < 4; rr++) {
            if (g == rr) {
                mlb[r0l * 2]           = m0;
                mlb[r0l * 2 + 1]       = l0;
                mlb[(r0l + 8) * 2]     = m1;
                mlb[(r0l + 8) * 2 + 1] = l1;
                #pragma unroll
                for (int nh = 0; nh < 8; nh++) {
                    int c = nh * 8 + tg * 2;
                    *(float2*)&obuf[r0l * 68 + c]       = make_float2(O[nh][0], O[nh][1]);
                    *(float2*)&obuf[(r0l + 8) * 68 + c] = make_float2(O[nh][2], O[nh][3]);
                }
            }
            __syncthreads();
            if (g == 0) {
                float mb0 = mlb[r0l * 2],       lb0 = mlb[r0l * 2 + 1];
                float mb1 = mlb[(r0l + 8) * 2], lb1 = mlb[(r0l + 8) * 2 + 1];
                float M0 = fmaxf(m0, mb0), M1 = fmaxf(m1, mb1);
                float ea0 = exp2f(m0 - M0),  eb0 = exp2f(mb0 - M0);
                float ea1 = exp2f(m1 - M1),  eb1 = exp2f(mb1 - M1);
                l0 = l0 * ea0 + lb0 * eb0;
                l1 = l1 * ea1 + lb1 * eb1;
                m0 = M0; m1 = M1;
                #pragma unroll
                for (int nh = 0; nh < 8; nh++) {
                    int c = nh * 8 + tg * 2;
                    float2 ob0 = *(float2*)&obuf[r0l * 68 + c];
                    float2 ob1 = *(float2*)&obuf[(r0l + 8) * 68 + c];
                    O[nh][0] = O[nh][0] * ea0 + ob0.x * eb0;
                    O[nh][1] = O[nh][1] * ea0 + ob0.y * eb0;
                    O[nh][2] = O[nh][2] * ea1 + ob1.x * eb1;
                    O[nh][3] = O[nh][3] * ea1 + ob1.y * eb1;
                }
            }
            __syncthreads();
        }

        if (g == 0) {
            const float inv0 = 1.f / l0, inv1 = 1.f / l1;
            const int r = qbase + r0l;
            #pragma unroll
            for (int nh = 0; nh < 8; nh++) {
                int c = nh * 8 + tg * 2;
                *(float2*)(out + bOff + (size_t)r * HD + c) =
                    make_float2(O[nh][0] * inv0, O[nh][1] * inv0);
                *(float2*)(out + bOff + (size_t)(r + 8) * HD + c) =
                    make_float2(O[nh][2] * inv1, O[nh][3] * inv1);
            }
        }
        #undef ISSUE_CP
    }
}

// ---------------------------------------------------------------------------
extern "C" void kernel_launch(void* const* d_in, const int* in_sizes, int n_in,
                              void* d_out, int out_size)
{
    const float* x  = (const float*)d_in[0];
    const float* Wq = (const float*)d_in[1];
    const float* bq = (const float*)d_in[2];
    const float* Wk = (const float*)d_in[3];
    const float* bk = (const float*)d_in[4];
    const float* Wv = (const float*)d_in[5];
    const float* bv = (const float*)d_in[6];
    float* out = (float*)d_out;

    cudaFuncSetAttribute(qkv_kernel,  cudaFuncAttributeMaxDynamicSharedMemorySize, QKV_SMEM);
    cudaFuncSetAttribute(attn_kernel, cudaFuncAttributeMaxDynamicSharedMemorySize, ATTN_SMEM);

    prep_w<<<192, 256>>>(Wq, Wk, Wv);
    qkv_kernel<<<(NB * SEQ) / 64, 256, QKV_SMEM>>>(x, bq, bk, bv);
    attn_kernel<<<dim3(16, NB), 512, ATTN_SMEM>>>(out);
}

// round 16
// speedup vs baseline: 2.7871x; 1.0684x over previous
#include <cuda_runtime.h>
#include <cuda_fp16.h>
#include <cstdint>

#define NB   8
#define SEQ  2048
#define ED   1024
#define HD   64

__device__ float    g_q[NB * SEQ * HD];
__device__ uint32_t g_k16[NB * SEQ * 32];   // fp16x2-packed K
__device__ uint32_t g_v16[NB * SEQ * 32];   // fp16x2-packed V
__device__ uint32_t g_w16[192 * 512];       // fp16x2-packed W (q|k|v stacked)

// ---------------- helpers ----------------
__device__ __forceinline__ void mma_f16(float* d, const uint32_t* a, const uint32_t* b) {
    asm("mma.sync.aligned.m16n8k16.row.col.f32.f16.f16.f32 "
        "{%0,%1,%2,%3}, {%4,%5,%6,%7}, {%8,%9}, {%0,%1,%2,%3};"
        : "+f"(d[0]), "+f"(d[1]), "+f"(d[2]), "+f"(d[3])
        : "r"(a[0]), "r"(a[1]), "r"(a[2]), "r"(a[3]), "r"(b[0]), "r"(b[1]));
}
__device__ __forceinline__ uint32_t packh2(float a, float b) {
    __half2 h = __floats2half2_rn(a, b);
    return *(uint32_t*)&h;
}
__device__ __forceinline__ uint32_t ex2h2(uint32_t in) {
    uint32_t r;
    asm("ex2.approx.f16x2 %0, %1;" : "=r"(r) : "r"(in));
    return r;
}
__device__ __forceinline__ void split2h(float a, float b, uint32_t& hi, uint32_t& lo) {
    __half2 h2 = __floats2half2_rn(a, b);
    float ar = a - __half2float(__low2half(h2));
    float br = b - __half2float(__high2half(h2));
    __half2 l2 = __floats2half2_rn(ar, br);
    hi = *(uint32_t*)&h2;
    lo = *(uint32_t*)&l2;
}

#define CP_ASYNC16(dst, src) \
    asm volatile("cp.async.cg.shared.global [%0], [%1], 16;" :: "r"(dst), "l"(src) : "memory")
#define CP_COMMIT() asm volatile("cp.async.commit_group;" ::: "memory")
#define CP_WAIT1()  asm volatile("cp.async.wait_group 1;" ::: "memory")
#define CP_WAIT0()  asm volatile("cp.async.wait_group 0;" ::: "memory")
#define LDSM4T(d0, d1, d2, d3, a) \
    asm volatile("ldmatrix.sync.aligned.m8n8.x4.trans.shared.b16 {%0,%1,%2,%3}, [%4];" \
                 : "=r"(d0), "=r"(d1), "=r"(d2), "=r"(d3) : "r"(a))
#define LDSM4(d0, d1, d2, d3, a) \
    asm volatile("ldmatrix.sync.aligned.m8n8.x4.shared.b16 {%0,%1,%2,%3}, [%4];" \
                 : "=r"(d0), "=r"(d1), "=r"(d2), "=r"(d3) : "r"(a))

extern __shared__ uint32_t sbuf[];

// ---------------------------------------------------------------------------
// Prep: pack W (q|k|v stacked, 192 x 1024 fp32) into fp16 pairs.
// ---------------------------------------------------------------------------
__global__ void prep_w(const float* __restrict__ Wq, const float* __restrict__ Wk,
                       const float* __restrict__ Wv)
{
    int idx = blockIdx.x * 256 + threadIdx.x;
    int row = idx >> 8;
    int f4  = idx & 255;
    const float* src = (row < 64)  ? Wq + (size_t)row * ED
                     : (row < 128) ? Wk + (size_t)(row - 64) * ED
                                   : Wv + (size_t)(row - 128) * ED;
    float4 f = *(const float4*)(src + f4 * 4);
    g_w16[row * 512 + f4 * 2]     = packh2(f.x, f.y);
    g_w16[row * 512 + f4 * 2 + 1] = packh2(f.z, f.w);
}

// ---------------------------------------------------------------------------
// QKV v4: fp16 m16n8k16, mixed precision (q: xh+xl 2-term, k/v: xh only).
// Warp grid 4m x 2n (one m16 tile per warp -> A-fragment splits halved).
// Column blocks interleaved bI = wn + ni*2 (each warp owns 4 q-blocks).
// cp.async double-buffered (x raw fp32, split at fragment-load; W fp16).
// ---------------------------------------------------------------------------
#define QKV_SMEM (51200)

__global__ __launch_bounds__(256, 2)
void qkv_kernel(const float* __restrict__ x,
                const float* __restrict__ bq, const float* __restrict__ bk,
                const float* __restrict__ bv)
{
    const int t    = threadIdx.x;
    const int lane = t & 31;
    const int wid  = t >> 5;
    const int wm   = wid & 3;       // m16 tile 0..3
    const int wn   = wid >> 2;      // column interleave base 0..1
    const int gq   = lane >> 2;
    const int tg   = lane & 3;
    const size_t rowBase = (size_t)blockIdx.x * 64;

    const uint32_t smem0 = (uint32_t)__cvta_generic_to_shared(sbuf);

    float acc[12][4];
    #pragma unroll
    for (int ni = 0; ni < 12; ni++)
        #pragma unroll
        for (int j = 0; j < 4; j++) acc[ni][j] = 0.f;

    #define QISSUE(CH, BUFI) do {                                                  \
        uint32_t dstX = smem0 + (BUFI) * 10240;                                    \
        uint32_t dstW = smem0 + 20480 + (BUFI) * 15360;                            \
        _Pragma("unroll")                                                          \
        for (int i = 0; i < 2; i++) {                                              \
            int idx = t + i * 256;                                                 \
            int row = idx >> 3, c8 = idx & 7;                                      \
            CP_ASYNC16(dstX + (uint32_t)(row * 160 + c8 * 16),                     \
                       x + (rowBase + row) * ED + (CH) * 32 + c8 * 4);             \
        }                                                                          \
        _Pragma("unroll")                                                          \
        for (int i = 0; i < 3; i++) {                                              \
            int idx = t + i * 256;                                                 \
            int row = idx >> 2, c4 = (idx & 3) * 4;                                \
            CP_ASYNC16(dstW + (uint32_t)(row * 80 + c4 * 4),                       \
                       g_w16 + (size_t)row * 512 + (CH) * 16 + c4);                \
        }                                                                          \
        CP_COMMIT();                                                               \
    } while (0)

    QISSUE(0, 0);
    QISSUE(1, 1);

    for (int ch = 0; ch < 32; ch++) {
        const int cur = ch & 1;
        if (ch + 1 < 32) CP_WAIT1(); else CP_WAIT0();
        __syncthreads();

        const float*    xst = (const float*)sbuf + cur * 2560;
        const uint32_t* wst = sbuf + 5120 + cur * 3840;

        #pragma unroll
        for (int kk = 0; kk < 2; kk++) {
            const int c0 = kk * 8 + tg;
            // B fragments: 12 interleaved blocks
            uint32_t bh[12][2];
            #pragma unroll
            for (int ni = 0; ni < 12; ni++) {
                int n0 = (wn + ni * 2) * 8 + gq;
                bh[ni][0] = wst[n0 * 20 + c0];
                bh[ni][1] = wst[n0 * 20 + c0 + 4];
            }
            // A fragment (single m16 tile): fp32 pairs, split hi/lo at use
            uint32_t ah[4], al[4];
            {
                const int col = kk * 16 + tg * 2;
                const int r0 = wm * 16 + gq;
                float2 f00 = *(const float2*)&xst[r0 * 40 + col];
                float2 f10 = *(const float2*)&xst[(r0 + 8) * 40 + col];
                float2 f01 = *(const float2*)&xst[r0 * 40 + col + 8];
                float2 f11 = *(const float2*)&xst[(r0 + 8) * 40 + col + 8];
                split2h(f00.x, f00.y, ah[0], al[0]);
                split2h(f10.x, f10.y, ah[1], al[1]);
                split2h(f01.x, f01.y, ah[2], al[2]);
                split2h(f11.x, f11.y, ah[3], al[3]);
            }
            // hi term: all 12 blocks
            #pragma unroll
            for (int ni = 0; ni < 12; ni++) mma_f16(acc[ni], ah, bh[ni]);
            // lo term: q blocks only (bI = wn + ni*2 < 8 <=> ni < 4)
            #pragma unroll
            for (int ni = 0; ni < 4; ni++) mma_f16(acc[ni], al, bh[ni]);
        }

        __syncthreads();
        if (ch + 2 < 32) QISSUE(ch + 2, cur);
    }
    #undef QISSUE

    #pragma unroll
    for (int ni = 0; ni < 12; ni++) {
        const int gc0 = (wn + ni * 2) * 8;
        const int wi  = gc0 >> 6;
        const int h0  = (gc0 & 63) + tg * 2;
        const float* bp = (wi == 0) ? bq : (wi == 1) ? bk : bv;
        const float b0 = bp[h0], b1 = bp[h0 + 1];
        size_t r = rowBase + wm * 16 + gq;
        float v0 = acc[ni][0] + b0, v1 = acc[ni][1] + b1;
        float v2 = acc[ni][2] + b0, v3 = acc[ni][3] + b1;
        if (wi == 0) {
            *(float2*)(g_q + r * HD + h0)       = make_float2(v0, v1);
            *(float2*)(g_q + (r + 8) * HD + h0) = make_float2(v2, v3);
        } else {
            uint32_t* outp = (wi == 1) ? g_k16 : g_v16;
            int hp = ((gc0 & 63) >> 1) + tg;
            outp[r * 32 + hp]       = packh2(v0, v1);
            outp[(r + 8) * 32 + hp] = packh2(v2, v3);
        }
    }
}

// ---------------------------------------------------------------------------
// Causal flash attention v7: like v6 but K B-fragments loaded via
// non-transposed ldmatrix.x4 (16 LDSM/round instead of 64 LDS.64).
// ---------------------------------------------------------------------------
#define GROUP_BAR(gid) asm volatile("bar.sync %0, 128;" :: "r"((gid) + 1) : "memory")
#define ATTN_SMEM (147456)

__global__ __launch_bounds__(512, 1)
void attn_kernel(float* __restrict__ out)
{
    const int t    = threadIdx.x;
    const int lane = t & 31;
    const int wid  = t >> 5;
    const int g    = wid >> 2;
    const int qb   = wid & 3;
    const int gq   = lane >> 2;
    const int tg   = lane & 3;
    const int tl   = t & 127;
    const int b    = blockIdx.y;
    const size_t bOff  = (size_t)b * SEQ * HD;
    const size_t bOffH = (size_t)b * SEQ * 32;

    const uint32_t gbase = g * 9216;
    const uint32_t smem0 = (uint32_t)__cvta_generic_to_shared(sbuf);
    float* obuf = (float*)sbuf;
    float* mlb  = (float*)(sbuf + 4352);

    // V ldmatrix.trans lane offset
    const uint32_t vlane = (uint32_t)(((lane & 7) + ((lane >> 3) & 1) * 8) * 144
                                      + (lane >> 4) * 16);
    // K ldmatrix (non-trans) lane offset: rows within block + half-select +
    // second-block select
    const uint32_t klane = (uint32_t)((lane & 7) * 144 + ((lane >> 3) & 1) * 16
                                      + ((lane >> 4) & 1) * 1152);

    const float SC2 = 0.18033688f;     // log2(e) / 8

    for (int pass = 0; pass < 2; pass++) {
        __syncthreads();
        const int qt = pass ? (31 - blockIdx.x) : blockIdx.x;
        const int qbase = qt * 64;
        const int r0l = qb * 16 + gq;

        uint32_t qh2[4][4], ql2[4][4];
        {
            const float* qp = g_q + bOff + (size_t)(qbase + r0l) * HD;
            #pragma unroll
            for (int c = 0; c < 4; c++) {
                int c0 = c * 16 + tg * 2;
                float2 f00 = *(const float2*)(qp + c0);
                float2 f10 = *(const float2*)(qp + 8 * HD + c0);
                float2 f01 = *(const float2*)(qp + c0 + 8);
                float2 f11 = *(const float2*)(qp + 8 * HD + c0 + 8);
                split2h(f00.x * SC2, f00.y * SC2, qh2[c][0], ql2[c][0]);
                split2h(f10.x * SC2, f10.y * SC2, qh2[c][1], ql2[c][1]);
                split2h(f01.x * SC2, f01.y * SC2, qh2[c][2], ql2[c][2]);
                split2h(f11.x * SC2, f11.y * SC2, qh2[c][3], ql2[c][3]);
            }
        }

        float m0 = -1e30f, m1 = -1e30f;
        float lacc[4] = {0.f, 0.f, 0.f, 0.f};
        float O[8][4];
        #pragma unroll
        for (int nh = 0; nh < 8; nh++)
            #pragma unroll
            for (int j = 0; j < 4; j++) O[nh][j] = 0.f;

        const int ng = (qt >= g) ? (((qt - g) >> 2) + 1) : 0;

        #define ISSUE_CP(KB, BUFI) do {                                           \
            uint32_t dstK = smem0 + (gbase + (BUFI) * 4608) * 4;                  \
            uint32_t dstV = dstK + 9216;                                          \
            _Pragma("unroll")                                                     \
            for (int i = 0; i < 4; i++) {                                         \
                int idx = tl + 128 * i;                                           \
                int row = idx >> 3, c = idx & 7;                                  \
                uint32_t so = (uint32_t)(row * 144 + c * 16);                     \
                const uint32_t* sk = g_k16 + bOffH + (size_t)((KB) + row) * 32 + c * 4; \
                const uint32_t* sv = g_v16 + bOffH + (size_t)((KB) + row) * 32 + c * 4; \
                CP_ASYNC16(dstK + so, sk);                                        \
                CP_ASYNC16(dstV + so, sv);                                        \
            }                                                                     \
            CP_COMMIT();                                                          \
        } while (0)

        if (ng > 0) ISSUE_CP(g * 64, 0);
        if (ng > 1) ISSUE_CP((4 + g) * 64, 1);

        for (int r = 0; r < ng; r++) {
            const int cur = r & 1;
            const int kbase = (4 * r + g) * 64;
            const uint32_t kbytes = smem0 + (gbase + cur * 4608) * 4;
            const uint32_t vbytes = kbytes + 9216;

            if (r + 1 < ng) CP_WAIT1(); else CP_WAIT0();
            GROUP_BAR(g);

            float s[8][4];
            #pragma unroll
            for (int nk = 0; nk < 8; nk++)
                #pragma unroll
                for (int j2 = 0; j2 < 4; j2++) s[nk][j2] = 0.f;

            #pragma unroll
            for (int c = 0; c < 4; c++) {
                uint32_t bfr[8][2];
                #pragma unroll
                for (int p = 0; p < 4; p++) {
                    uint32_t d0, d1, d2, d3;
                    uint32_t addr = kbytes + klane + (uint32_t)(p * 2304 + c * 32);
                    LDSM4(d0, d1, d2, d3, addr);
                    bfr[2 * p][0]     = d0;
                    bfr[2 * p][1]     = d1;
                    bfr[2 * p + 1][0] = d2;
                    bfr[2 * p + 1][1] = d3;
                }
                #pragma unroll
                for (int nk = 0; nk < 8; nk++) mma_f16(s[nk], qh2[c], bfr[nk]);
                #pragma unroll
                for (int nk = 0; nk < 8; nk++) mma_f16(s[nk], ql2[c], bfr[nk]);
            }

            if (kbase == qbase) {
                const int row0 = r0l, row1 = r0l + 8;
                #pragma unroll
                for (int nk = 0; nk < 8; nk++) {
                    int c = nk * 8 + tg * 2;
                    if (c     > row0) s[nk][0] = -1e30f;
                    if (c + 1 > row0) s[nk][1] = -1e30f;
                    if (c     > row1) s[nk][2] = -1e30f;
                    if (c + 1 > row1) s[nk][3] = -1e30f;
                }
            }

            float rm0 = -1e30f, rm1 = -1e30f;
            #pragma unroll
            for (int nk = 0; nk < 8; nk++) {
                rm0 = fmaxf(rm0, fmaxf(s[nk][0], s[nk][1]));
                rm1 = fmaxf(rm1, fmaxf(s[nk][2], s[nk][3]));
            }
            rm0 = fmaxf(rm0, __shfl_xor_sync(0xffffffffu, rm0, 1));
            rm0 = fmaxf(rm0, __shfl_xor_sync(0xffffffffu, rm0, 2));
            rm1 = fmaxf(rm1, __shfl_xor_sync(0xffffffffu, rm1, 1));
            rm1 = fmaxf(rm1, __shfl_xor_sync(0xffffffffu, rm1, 2));

            float mn0 = fmaxf(m0, rm0), mn1 = fmaxf(m1, rm1);
            float a0 = exp2f(m0 - mn0), a1 = exp2f(m1 - mn1);
            m0 = mn0; m1 = mn1;
            lacc[0] *= a0; lacc[1] *= a0; lacc[2] *= a1; lacc[3] *= a1;
            #pragma unroll
            for (int nh = 0; nh < 8; nh++) {
                O[nh][0] *= a0; O[nh][1] *= a0;
                O[nh][2] *= a1; O[nh][3] *= a1;
            }

            const uint32_t ones2[2] = {0x3C003C00u, 0x3C003C00u};
            #pragma unroll
            for (int c = 0; c < 4; c++) {
                uint32_t pa[4];
                pa[0] = ex2h2(packh2(s[2 * c][0]     - m0, s[2 * c][1]     - m0));
                pa[1] = ex2h2(packh2(s[2 * c][2]     - m1, s[2 * c][3]     - m1));
                pa[2] = ex2h2(packh2(s[2 * c + 1][0] - m0, s[2 * c + 1][1] - m0));
                pa[3] = ex2h2(packh2(s[2 * c + 1][2] - m1, s[2 * c + 1][3] - m1));
                #pragma unroll
                for (int hb = 0; hb < 4; hb++) {
                    uint32_t d0, d1, d2, d3;
                    uint32_t addr = vbytes + vlane + (uint32_t)(c * 16 * 144 + hb * 32);
                    LDSM4T(d0, d1, d2, d3, addr);
                    uint32_t vb0[2] = {d0, d1};
                    uint32_t vb1[2] = {d2, d3};
                    mma_f16(O[2 * hb],     pa, vb0);
                    mma_f16(O[2 * hb + 1], pa, vb1);
                }
                mma_f16(lacc, pa, ones2);
            }

            GROUP_BAR(g);
            if (r + 2 < ng) ISSUE_CP((4 * (r + 2) + g) * 64, cur);
        }

        float l0 = lacc[0], l1 = lacc[2];

        __syncthreads();
        #pragma unroll
        for (int rr = 1; rr < 4; rr++) {
            if (g == rr) {
                mlb[r0l * 2]           = m0;
                mlb[r0l * 2 + 1]       = l0;
                mlb[(r0l + 8) * 2]     = m1;
                mlb[(r0l + 8) * 2 + 1] = l1;
                #pragma unroll
                for (int nh = 0; nh < 8; nh++) {
                    int c = nh * 8 + tg * 2;
                    *(float2*)&obuf[r0l * 68 + c]       = make_float2(O[nh][0], O[nh][1]);
                    *(float2*)&obuf[(r0l + 8) * 68 + c] = make_float2(O[nh][2], O[nh][3]);
                }
            }
            __syncthreads();
            if (g == 0) {
                float mb0 = mlb[r0l * 2],       lb0 = mlb[r0l * 2 + 1];
                float mb1 = mlb[(r0l + 8) * 2], lb1 = mlb[(r0l + 8) * 2 + 1];
                float M0 = fmaxf(m0, mb0), M1 = fmaxf(m1, mb1);
                float ea0 = exp2f(m0 - M0),  eb0 = exp2f(mb0 - M0);
                float ea1 = exp2f(m1 - M1),  eb1 = exp2f(mb1 - M1);
                l0 = l0 * ea0 + lb0 * eb0;
                l1 = l1 * ea1 + lb1 * eb1;
                m0 = M0; m1 = M1;
                #pragma unroll
                for (int nh = 0; nh < 8; nh++) {
                    int c = nh * 8 + tg * 2;
                    float2 ob0 = *(float2*)&obuf[r0l * 68 + c];
                    float2 ob1 = *(float2*)&obuf[(r0l + 8) * 68 + c];
                    O[nh][0] = O[nh][0] * ea0 + ob0.x * eb0;
                    O[nh][1] = O[nh][1] * ea0 + ob0.y * eb0;
                    O[nh][2] = O[nh][2] * ea1 + ob1.x * eb1;
                    O[nh][3] = O[nh][3] * ea1 + ob1.y * eb1;
                }
            }
            __syncthreads();
        }

        if (g == 0) {
            const float inv0 = 1.f / l0, inv1 = 1.f / l1;
            const int r = qbase + r0l;
            #pragma unroll
            for (int nh = 0; nh < 8; nh++) {
                int c = nh * 8 + tg * 2;
                *(float2*)(out + bOff + (size_t)r * HD + c) =
                    make_float2(O[nh][0] * inv0, O[nh][1] * inv0);
                *(float2*)(out + bOff + (size_t)(r + 8) * HD + c) =
                    make_float2(O[nh][2] * inv1, O[nh][3] * inv1);
            }
        }
        #undef ISSUE_CP
    }
}

// ---------------------------------------------------------------------------
extern "C" void kernel_launch(void* const* d_in, const int* in_sizes, int n_in,
                              void* d_out, int out_size)
{
    const float* x  = (const float*)d_in[0];
    const float* Wq = (const float*)d_in[1];
    const float* bq = (const float*)d_in[2];
    const float* Wk = (const float*)d_in[3];
    const float* bk = (const float*)d_in[4];
    const float* Wv = (const float*)d_in[5];
    const float* bv = (const float*)d_in[6];
    float* out = (float*)d_out;

    cudaFuncSetAttribute(qkv_kernel,  cudaFuncAttributeMaxDynamicSharedMemorySize, QKV_SMEM);
    cudaFuncSetAttribute(attn_kernel, cudaFuncAttributeMaxDynamicSharedMemorySize, ATTN_SMEM);

    prep_w<<<192, 256>>>(Wq, Wk, Wv);
    qkv_kernel<<<(NB * SEQ) / 64, 256, QKV_SMEM>>>(x, bq, bk, bv);
    attn_kernel<<<dim3(16, NB), 512, ATTN_SMEM>>>(out);
}

// round 17
// speedup vs baseline: 3.2287x; 1.1584x over previous
#include <cuda_runtime.h>
#include <cuda_fp16.h>
#include <cstdint>

#define NB   8
#define SEQ  2048
#define ED   1024
#define HD   64

__device__ uint32_t g_q16[NB * SEQ * 32];   // fp16x2-packed Q (scale NOT folded)
__device__ uint32_t g_k16[NB * SEQ * 32];   // fp16x2-packed K (log2e/8 folded in)
__device__ uint32_t g_v16[NB * SEQ * 32];   // fp16x2-packed V
__device__ uint32_t g_w16[192 * 512];       // fp16x2-packed W (q|k|v stacked)

// ---------------- helpers ----------------
__device__ __forceinline__ void mma_f16(float* d, const uint32_t* a, const uint32_t* b) {
    asm("mma.sync.aligned.m16n8k16.row.col.f32.f16.f16.f32 "
        "{%0,%1,%2,%3}, {%4,%5,%6,%7}, {%8,%9}, {%0,%1,%2,%3};"
        : "+f"(d[0]), "+f"(d[1]), "+f"(d[2]), "+f"(d[3])
        : "r"(a[0]), "r"(a[1]), "r"(a[2]), "r"(a[3]), "r"(b[0]), "r"(b[1]));
}
__device__ __forceinline__ uint32_t packh2(float a, float b) {
    __half2 h = __floats2half2_rn(a, b);
    return *(uint32_t*)&h;
}
__device__ __forceinline__ uint32_t ex2h2(uint32_t in) {
    uint32_t r;
    asm("ex2.approx.f16x2 %0, %1;" : "=r"(r) : "r"(in));
    return r;
}

#define CP_ASYNC16(dst, src) \
    asm volatile("cp.async.cg.shared.global [%0], [%1], 16;" :: "r"(dst), "l"(src) : "memory")
#define CP_COMMIT() asm volatile("cp.async.commit_group;" ::: "memory")
#define CP_WAIT1()  asm volatile("cp.async.wait_group 1;" ::: "memory")
#define CP_WAIT0()  asm volatile("cp.async.wait_group 0;" ::: "memory")
#define LDSM4T(d0, d1, d2, d3, a) \
    asm volatile("ldmatrix.sync.aligned.m8n8.x4.trans.shared.b16 {%0,%1,%2,%3}, [%4];" \
                 : "=r"(d0), "=r"(d1), "=r"(d2), "=r"(d3) : "r"(a))
#define LDSM4(d0, d1, d2, d3, a) \
    asm volatile("ldmatrix.sync.aligned.m8n8.x4.shared.b16 {%0,%1,%2,%3}, [%4];" \
                 : "=r"(d0), "=r"(d1), "=r"(d2), "=r"(d3) : "r"(a))

extern __shared__ uint32_t sbuf[];

// ---------------------------------------------------------------------------
// Prep: pack W (q|k|v stacked, 192 x 1024 fp32) into fp16 pairs.
// ---------------------------------------------------------------------------
__global__ void prep_w(const float* __restrict__ Wq, const float* __restrict__ Wk,
                       const float* __restrict__ Wv)
{
    int idx = blockIdx.x * 256 + threadIdx.x;
    int row = idx >> 8;
    int f4  = idx & 255;
    const float* src = (row < 64)  ? Wq + (size_t)row * ED
                     : (row < 128) ? Wk + (size_t)(row - 64) * ED
                                   : Wv + (size_t)(row - 128) * ED;
    float4 f = *(const float4*)(src + f4 * 4);
    g_w16[row * 512 + f4 * 2]     = packh2(f.x, f.y);
    g_w16[row * 512 + f4 * 2 + 1] = packh2(f.z, f.w);
}

// ---------------------------------------------------------------------------
// QKV v5: fp16 m16n8k16, single-term (xh*w). All outputs packed fp16; the
// softmax scale log2e/8 is folded into K here. 12 MMAs/warp/kstep.
// Warp grid 4m x 2n; blocks interleaved bI = wn + ni*2.
// cp.async double-buffered (x raw fp32, packed at fragment-load; W fp16).
// ---------------------------------------------------------------------------
#define QKV_SMEM (51200)

__global__ __launch_bounds__(256, 2)
void qkv_kernel(const float* __restrict__ x,
                const float* __restrict__ bq, const float* __restrict__ bk,
                const float* __restrict__ bv)
{
    const int t    = threadIdx.x;
    const int lane = t & 31;
    const int wid  = t >> 5;
    const int wm   = wid & 3;       // m16 tile 0..3
    const int wn   = wid >> 2;      // column interleave base 0..1
    const int gq   = lane >> 2;
    const int tg   = lane & 3;
    const size_t rowBase = (size_t)blockIdx.x * 64;

    const uint32_t smem0 = (uint32_t)__cvta_generic_to_shared(sbuf);
    const float SC2 = 0.18033688f;  // log2(e) / 8, folded into K

    float acc[12][4];
    #pragma unroll
    for (int ni = 0; ni < 12; ni++)
        #pragma unroll
        for (int j = 0; j < 4; j++) acc[ni][j] = 0.f;

    #define QISSUE(CH, BUFI) do {                                                  \
        uint32_t dstX = smem0 + (BUFI) * 10240;                                    \
        uint32_t dstW = smem0 + 20480 + (BUFI) * 15360;                            \
        _Pragma("unroll")                                                          \
        for (int i = 0; i < 2; i++) {                                              \
            int idx = t + i * 256;                                                 \
            int row = idx >> 3, c8 = idx & 7;                                      \
            CP_ASYNC16(dstX + (uint32_t)(row * 160 + c8 * 16),                     \
                       x + (rowBase + row) * ED + (CH) * 32 + c8 * 4);             \
        }                                                                          \
        _Pragma("unroll")                                                          \
        for (int i = 0; i < 3; i++) {                                              \
            int idx = t + i * 256;                                                 \
            int row = idx >> 2, c4 = (idx & 3) * 4;                                \
            CP_ASYNC16(dstW + (uint32_t)(row * 80 + c4 * 4),                       \
                       g_w16 + (size_t)row * 512 + (CH) * 16 + c4);                \
        }                                                                          \
        CP_COMMIT();                                                               \
    } while (0)

    QISSUE(0, 0);
    QISSUE(1, 1);

    for (int ch = 0; ch < 32; ch++) {
        const int cur = ch & 1;
        if (ch + 1 < 32) CP_WAIT1(); else CP_WAIT0();
        __syncthreads();

        const float*    xst = (const float*)sbuf + cur * 2560;
        const uint32_t* wst = sbuf + 5120 + cur * 3840;

        #pragma unroll
        for (int kk = 0; kk < 2; kk++) {
            const int c0 = kk * 8 + tg;
            uint32_t bh[12][2];
            #pragma unroll
            for (int ni = 0; ni < 12; ni++) {
                int n0 = (wn + ni * 2) * 8 + gq;
                bh[ni][0] = wst[n0 * 20 + c0];
                bh[ni][1] = wst[n0 * 20 + c0 + 4];
            }
            uint32_t ah[4];
            {
                const int col = kk * 16 + tg * 2;
                const int r0 = wm * 16 + gq;
                float2 f00 = *(const float2*)&xst[r0 * 40 + col];
                float2 f10 = *(const float2*)&xst[(r0 + 8) * 40 + col];
                float2 f01 = *(const float2*)&xst[r0 * 40 + col + 8];
                float2 f11 = *(const float2*)&xst[(r0 + 8) * 40 + col + 8];
                ah[0] = packh2(f00.x, f00.y);
                ah[1] = packh2(f10.x, f10.y);
                ah[2] = packh2(f01.x, f01.y);
                ah[3] = packh2(f11.x, f11.y);
            }
            #pragma unroll
            for (int ni = 0; ni < 12; ni++) mma_f16(acc[ni], ah, bh[ni]);
        }

        __syncthreads();
        if (ch + 2 < 32) QISSUE(ch + 2, cur);
    }
    #undef QISSUE

    #pragma unroll
    for (int ni = 0; ni < 12; ni++) {
        const int gc0 = (wn + ni * 2) * 8;
        const int wi  = gc0 >> 6;
        const int h0  = (gc0 & 63) + tg * 2;
        const float* bp = (wi == 0) ? bq : (wi == 1) ? bk : bv;
        const float b0 = bp[h0], b1 = bp[h0 + 1];
        size_t r = rowBase + wm * 16 + gq;
        float v0 = acc[ni][0] + b0, v1 = acc[ni][1] + b1;
        float v2 = acc[ni][2] + b0, v3 = acc[ni][3] + b1;
        if (wi == 1) { v0 *= SC2; v1 *= SC2; v2 *= SC2; v3 *= SC2; }  // fold scale into K
        uint32_t* outp = (wi == 0) ? g_q16 : (wi == 1) ? g_k16 : g_v16;
        int hp = ((gc0 & 63) >> 1) + tg;
        outp[r * 32 + hp]       = packh2(v0, v1);
        outp[(r + 8) * 32 + hp] = packh2(v2, v3);
    }
}

// ---------------------------------------------------------------------------
// Causal flash attention v8: q single-fp16 loaded directly as A-fragments
// (scale pre-folded into K at qkv) -> S loop is 32 MMAs/round.
// ---------------------------------------------------------------------------
#define GROUP_BAR(gid) asm volatile("bar.sync %0, 128;" :: "r"((gid) + 1) : "memory")
#define ATTN_SMEM (147456)

__global__ __launch_bounds__(512, 1)
void attn_kernel(float* __restrict__ out)
{
    const int t    = threadIdx.x;
    const int lane = t & 31;
    const int wid  = t >> 5;
    const int g    = wid >> 2;
    const int qb   = wid & 3;
    const int gq   = lane >> 2;
    const int tg   = lane & 3;
    const int tl   = t & 127;
    const int b    = blockIdx.y;
    const size_t bOff  = (size_t)b * SEQ * HD;
    const size_t bOffH = (size_t)b * SEQ * 32;

    const uint32_t gbase = g * 9216;
    const uint32_t smem0 = (uint32_t)__cvta_generic_to_shared(sbuf);
    float* obuf = (float*)sbuf;
    float* mlb  = (float*)(sbuf + 4352);

    const uint32_t vlane = (uint32_t)(((lane & 7) + ((lane >> 3) & 1) * 8) * 144
                                      + (lane >> 4) * 16);
    const uint32_t klane = (uint32_t)((lane & 7) * 144 + ((lane >> 3) & 1) * 16
                                      + ((lane >> 4) & 1) * 1152);

    for (int pass = 0; pass < 2; pass++) {
        __syncthreads();
        const int qt = pass ? (31 - blockIdx.x) : blockIdx.x;
        const int qbase = qt * 64;
        const int r0l = qb * 16 + gq;

        // Q A-fragments: direct packed-fp16 loads (no split, no scale)
        uint32_t qh2[4][4];
        {
            const uint32_t* qp = g_q16 + bOffH + (size_t)(qbase + r0l) * 32;
            #pragma unroll
            for (int c = 0; c < 4; c++) {
                qh2[c][0] = qp[c * 8 + tg];
                qh2[c][1] = qp[8 * 32 + c * 8 + tg];
                qh2[c][2] = qp[c * 8 + tg + 4];
                qh2[c][3] = qp[8 * 32 + c * 8 + tg + 4];
            }
        }

        float m0 = -1e30f, m1 = -1e30f;
        float lacc[4] = {0.f, 0.f, 0.f, 0.f};
        float O[8][4];
        #pragma unroll
        for (int nh = 0; nh < 8; nh++)
            #pragma unroll
            for (int j = 0; j < 4; j++) O[nh][j] = 0.f;

        const int ng = (qt >= g) ? (((qt - g) >> 2) + 1) : 0;

        #define ISSUE_CP(KB, BUFI) do {                                           \
            uint32_t dstK = smem0 + (gbase + (BUFI) * 4608) * 4;                  \
            uint32_t dstV = dstK + 9216;                                          \
            _Pragma("unroll")                                                     \
            for (int i = 0; i < 4; i++) {                                         \
                int idx = tl + 128 * i;                                           \
                int row = idx >> 3, c = idx & 7;                                  \
                uint32_t so = (uint32_t)(row * 144 + c * 16);                     \
                const uint32_t* sk = g_k16 + bOffH + (size_t)((KB) + row) * 32 + c * 4; \
                const uint32_t* sv = g_v16 + bOffH + (size_t)((KB) + row) * 32 + c * 4; \
                CP_ASYNC16(dstK + so, sk);                                        \
                CP_ASYNC16(dstV + so, sv);                                        \
            }                                                                     \
            CP_COMMIT();                                                          \
        } while (0)

        if (ng > 0) ISSUE_CP(g * 64, 0);
        if (ng > 1) ISSUE_CP((4 + g) * 64, 1);

        for (int r = 0; r < ng; r++) {
            const int cur = r & 1;
            const int kbase = (4 * r + g) * 64;
            const uint32_t kbytes = smem0 + (gbase + cur * 4608) * 4;
            const uint32_t vbytes = kbytes + 9216;

            if (r + 1 < ng) CP_WAIT1(); else CP_WAIT0();
            GROUP_BAR(g);

            float s[8][4];
            #pragma unroll
            for (int nk = 0; nk < 8; nk++)
                #pragma unroll
                for (int j2 = 0; j2 < 4; j2++) s[nk][j2] = 0.f;

            #pragma unroll
            for (int c = 0; c < 4; c++) {
                uint32_t bfr[8][2];
                #pragma unroll
                for (int p = 0; p < 4; p++) {
                    uint32_t d0, d1, d2, d3;
                    uint32_t addr = kbytes + klane + (uint32_t)(p * 2304 + c * 32);
                    LDSM4(d0, d1, d2, d3, addr);
                    bfr[2 * p][0]     = d0;
                    bfr[2 * p][1]     = d1;
                    bfr[2 * p + 1][0] = d2;
                    bfr[2 * p + 1][1] = d3;
                }
                #pragma unroll
                for (int nk = 0; nk < 8; nk++) mma_f16(s[nk], qh2[c], bfr[nk]);
            }

            if (kbase == qbase) {
                const int row0 = r0l, row1 = r0l + 8;
                #pragma unroll
                for (int nk = 0; nk < 8; nk++) {
                    int c = nk * 8 + tg * 2;
                    if (c     > row0) s[nk][0] = -1e30f;
                    if (c + 1 > row0) s[nk][1] = -1e30f;
                    if (c     > row1) s[nk][2] = -1e30f;
                    if (c + 1 > row1) s[nk][3] = -1e30f;
                }
            }

            float rm0 = -1e30f, rm1 = -1e30f;
            #pragma unroll
            for (int nk = 0; nk < 8; nk++) {
                rm0 = fmaxf(rm0, fmaxf(s[nk][0], s[nk][1]));
                rm1 = fmaxf(rm1, fmaxf(s[nk][2], s[nk][3]));
            }
            rm0 = fmaxf(rm0, __shfl_xor_sync(0xffffffffu, rm0, 1));
            rm0 = fmaxf(rm0, __shfl_xor_sync(0xffffffffu, rm0, 2));
            rm1 = fmaxf(rm1, __shfl_xor_sync(0xffffffffu, rm1, 1));
            rm1 = fmaxf(rm1, __shfl_xor_sync(0xffffffffu, rm1, 2));

            float mn0 = fmaxf(m0, rm0), mn1 = fmaxf(m1, rm1);
            float a0 = exp2f(m0 - mn0), a1 = exp2f(m1 - mn1);
            m0 = mn0; m1 = mn1;
            lacc[0] *= a0; lacc[1] *= a0; lacc[2] *= a1; lacc[3] *= a1;
            #pragma unroll
            for (int nh = 0; nh < 8; nh++) {
                O[nh][0] *= a0; O[nh][1] *= a0;
                O[nh][2] *= a1; O[nh][3] *= a1;
            }

            const uint32_t ones2[2] = {0x3C003C00u, 0x3C003C00u};
            #pragma unroll
            for (int c = 0; c < 4; c++) {
                uint32_t pa[4];
                pa[0] = ex2h2(packh2(s[2 * c][0]     - m0, s[2 * c][1]     - m0));
                pa[1] = ex2h2(packh2(s[2 * c][2]     - m1, s[2 * c][3]     - m1));
                pa[2] = ex2h2(packh2(s[2 * c + 1][0] - m0, s[2 * c + 1][1] - m0));
                pa[3] = ex2h2(packh2(s[2 * c + 1][2] - m1, s[2 * c + 1][3] - m1));
                #pragma unroll
                for (int hb = 0; hb < 4; hb++) {
                    uint32_t d0, d1, d2, d3;
                    uint32_t addr = vbytes + vlane + (uint32_t)(c * 16 * 144 + hb * 32);
                    LDSM4T(d0, d1, d2, d3, addr);
                    uint32_t vb0[2] = {d0, d1};
                    uint32_t vb1[2] = {d2, d3};
                    mma_f16(O[2 * hb],     pa, vb0);
                    mma_f16(O[2 * hb + 1], pa, vb1);
                }
                mma_f16(lacc, pa, ones2);
            }

            GROUP_BAR(g);
            if (r + 2 < ng) ISSUE_CP((4 * (r + 2) + g) * 64, cur);
        }

        float l0 = lacc[0], l1 = lacc[2];

        __syncthreads();
        #pragma unroll
        for (int rr = 1; rr < 4; rr++) {
            if (g == rr) {
                mlb[r0l * 2]           = m0;
                mlb[r0l * 2 + 1]       = l0;
                mlb[(r0l + 8) * 2]     = m1;
                mlb[(r0l + 8) * 2 + 1] = l1;
                #pragma unroll
                for (int nh = 0; nh < 8; nh++) {
                    int c = nh * 8 + tg * 2;
                    *(float2*)&obuf[r0l * 68 + c]       = make_float2(O[nh][0], O[nh][1]);
                    *(float2*)&obuf[(r0l + 8) * 68 + c] = make_float2(O[nh][2], O[nh][3]);
                }
            }
            __syncthreads();
            if (g == 0) {
                float mb0 = mlb[r0l * 2],       lb0 = mlb[r0l * 2 + 1];
                float mb1 = mlb[(r0l + 8) * 2], lb1 = mlb[(r0l + 8) * 2 + 1];
                float M0 = fmaxf(m0, mb0), M1 = fmaxf(m1, mb1);
                float ea0 = exp2f(m0 - M0),  eb0 = exp2f(mb0 - M0);
                float ea1 = exp2f(m1 - M1),  eb1 = exp2f(mb1 - M1);
                l0 = l0 * ea0 + lb0 * eb0;
                l1 = l1 * ea1 + lb1 * eb1;
                m0 = M0; m1 = M1;
                #pragma unroll
                for (int nh = 0; nh < 8; nh++) {
                    int c = nh * 8 + tg * 2;
                    float2 ob0 = *(float2*)&obuf[r0l * 68 + c];
                    float2 ob1 = *(float2*)&obuf[(r0l + 8) * 68 + c];
                    O[nh][0] = O[nh][0] * ea0 + ob0.x * eb0;
                    O[nh][1] = O[nh][1] * ea0 + ob0.y * eb0;
                    O[nh][2] = O[nh][2] * ea1 + ob1.x * eb1;
                    O[nh][3] = O[nh][3] * ea1 + ob1.y * eb1;
                }
            }
            __syncthreads();
        }

        if (g == 0) {
            const float inv0 = 1.f / l0, inv1 = 1.f / l1;
            const int r = qbase + r0l;
            #pragma unroll
            for (int nh = 0; nh < 8; nh++) {
                int c = nh * 8 + tg * 2;
                *(float2*)(out + bOff + (size_t)r * HD + c) =
                    make_float2(O[nh][0] * inv0, O[nh][1] * inv0);
                *(float2*)(out + bOff + (size_t)(r + 8) * HD + c) =
                    make_float2(O[nh][2] * inv1, O[nh][3] * inv1);
            }
        }
        #undef ISSUE_CP
    }
}

// ---------------------------------------------------------------------------
extern "C" void kernel_launch(void* const* d_in, const int* in_sizes, int n_in,
                              void* d_out, int out_size)
{
    const float* x  = (const float*)d_in[0];
    const float* Wq = (const float*)d_in[1];
    const float* bq = (const float*)d_in[2];
    const float* Wk = (const float*)d_in[3];
    const float* bk = (const float*)d_in[4];
    const float* Wv = (const float*)d_in[5];
    const float* bv = (const float*)d_in[6];
    float* out = (float*)d_out;

    cudaFuncSetAttribute(qkv_kernel,  cudaFuncAttributeMaxDynamicSharedMemorySize, QKV_SMEM);
    cudaFuncSetAttribute(attn_kernel, cudaFuncAttributeMaxDynamicSharedMemorySize, ATTN_SMEM);

    prep_w<<<192, 256>>>(Wq, Wk, Wv);
    qkv_kernel<<<(NB * SEQ) / 64, 256, QKV_SMEM>>>(x, bq, bk, bv);
    attn_kernel<<<dim3(16, NB), 512, ATTN_SMEM>>>(out);
}